// round 11
// baseline (speedup 1.0000x reference)
#include <cuda_runtime.h>
#include <math.h>

#define C_ 10
#define Q_ 1000
#define R_ 1024
#define N_ 512
#define S_ 10000
#define M_ 10000          // C_*Q_
#define KSPLIT 8
#define CHUNK 1250        // M_/KSPLIT

// ---------------- static device scratch (no allocations allowed) ----------------
static __device__ float g_D[M_ * R_];                  // updated queues, 40.96 MB
static __device__ float g_Gp[KSPLIT][R_ * R_];         // SYRK partials, 33.5 MB
static __device__ float g_S[R_ * R_];                  // sigma -> L in place
static __device__ float g_mu[C_ * R_];
static __device__ float g_scores[N_ * C_];
static __device__ float g_scores_vos[C_ * C_];
static __device__ float g_eps_sel[C_ * R_];
static __device__ float g_vos[C_ * R_];
static __device__ float g_focal[N_];
static __device__ int   g_order[C_ * N_];
static __device__ int   g_cnt[C_];
static __device__ unsigned long long g_amax[C_];

// ---------------- per-class sample ordering (faithful sequential queue) ----------------
__global__ void order_kernel(const int* __restrict__ labels) {
    __shared__ int labs[N_];
    int tid = threadIdx.x;                   // 512 threads
    labs[tid] = labels[tid];
    if (tid < C_) { g_cnt[tid] = 0; g_amax[tid] = 0ull; }
    __syncthreads();
    int lab = labs[tid];
    int pos = 0;
    for (int j = 0; j < tid; j++) pos += (labs[j] == lab) ? 1 : 0;
    g_order[lab * N_ + pos] = tid;
    atomicAdd(&g_cnt[lab], 1);
}

// ---------------- materialize updated queue data D ----------------
// counters are full (Q), so every insert rolls: D[c] = id_data[c][k_c:] ++ class-c feats in order
__global__ void matD_kernel(const float* __restrict__ id_data, const float* __restrict__ box) {
    int row = blockIdx.x;                    // 0..9999
    int c = row / Q_, q = row - c * Q_;
    int k = g_cnt[c];
    const float* src;
    if (q < Q_ - k) src = id_data + (size_t)(c * Q_ + q + k) * R_;
    else            src = box + (size_t)g_order[c * N_ + q - (Q_ - k)] * R_;
    ((float4*)(g_D + (size_t)row * R_))[threadIdx.x] = ((const float4*)src)[threadIdx.x];
}

// ---------------- per-class mean ----------------
__global__ void mu_kernel() {
    int gid = blockIdx.x * 256 + threadIdx.x;   // 40 blocks -> 10240 = C_*R_
    int c = gid >> 10, r = gid & 1023;
    const float* base = g_D + ((size_t)(c * Q_)) * R_ + r;
    float s0 = 0.f, s1 = 0.f, s2 = 0.f, s3 = 0.f;
    for (int q = 0; q < Q_; q += 4) {
        s0 += base[(size_t)q * R_];
        s1 += base[(size_t)(q + 1) * R_];
        s2 += base[(size_t)(q + 2) * R_];
        s3 += base[(size_t)(q + 3) * R_];
    }
    g_mu[gid] = (s0 + s1 + s2 + s3) * (1.f / (float)Q_);
}

// ---------------- SYRK: Gp[z] += D_chunk^T D_chunk (lower 128x128 tiles) ----------------
#define SYRK_BODY(KK)                                                        \
    {                                                                        \
        float a[8], b[8];                                                    \
        *(float4*)&a[0] = *(const float4*)&As[KK][ty * 8];                   \
        *(float4*)&a[4] = *(const float4*)&As[KK][ty * 8 + 4];               \
        *(float4*)&b[0] = *(const float4*)&Bs[KK][tx * 8];                   \
        *(float4*)&b[4] = *(const float4*)&Bs[KK][tx * 8 + 4];               \
        _Pragma("unroll")                                                    \
        for (int r = 0; r < 8; r++)                                          \
            _Pragma("unroll")                                                \
            for (int c = 0; c < 8; c++)                                      \
                acc[r][c] = fmaf(a[r], b[c], acc[r][c]);                     \
    }

__global__ __launch_bounds__(256, 2) void syrk_kernel() {
    int t = blockIdx.x;
    int bi = 0;
    while ((bi + 1) * (bi + 2) / 2 <= t) bi++;
    int bj = t - bi * (bi + 1) / 2;

    __shared__ float As[16][132];
    __shared__ float Bs[16][132];

    int tid = threadIdx.x;
    int lr = tid >> 4, lc = tid & 15;        // load map: row 0..15, float4 col 0..15
    int tx = tid & 15, ty = tid >> 4;        // compute map: 16x16 threads, 8x8 micro

    int m0 = blockIdx.y * CHUNK;
    int m1 = m0 + CHUNK;

    float acc[8][8];
#pragma unroll
    for (int r = 0; r < 8; r++)
#pragma unroll
        for (int c = 0; c < 8; c++) acc[r][c] = 0.f;

    float4 pa0, pa1, pb0, pb1;
    {
        const float4* rp = (const float4*)(g_D + (size_t)(m0 + lr) * R_);
        pa0 = rp[bi * 32 + lc]; pa1 = rp[bi * 32 + lc + 16];
        pb0 = rp[bj * 32 + lc]; pb1 = rp[bj * 32 + lc + 16];
    }
    for (int mb = m0; mb < m1; mb += 16) {
        *(float4*)&As[lr][lc * 4]      = pa0;
        *(float4*)&As[lr][lc * 4 + 64] = pa1;
        *(float4*)&Bs[lr][lc * 4]      = pb0;
        *(float4*)&Bs[lr][lc * 4 + 64] = pb1;
        __syncthreads();
        int mn = mb + 16;
        if (mn < m1) {
            int m = mn + lr;
            if (m < m1) {
                const float4* rp = (const float4*)(g_D + (size_t)m * R_);
                pa0 = rp[bi * 32 + lc]; pa1 = rp[bi * 32 + lc + 16];
                pb0 = rp[bj * 32 + lc]; pb1 = rp[bj * 32 + lc + 16];
            } else {
                pa0 = pa1 = pb0 = pb1 = make_float4(0.f, 0.f, 0.f, 0.f);
            }
        }
        int kmax = (m1 - mb < 16) ? (m1 - mb) : 16;
        if (kmax == 16) {
#pragma unroll
            for (int kk = 0; kk < 16; kk++) SYRK_BODY(kk)
        } else {
            for (int kk = 0; kk < kmax; kk++) SYRK_BODY(kk)
        }
        __syncthreads();
    }
    float* gp = g_Gp[blockIdx.y];
    int r0 = bi * 128 + ty * 8, c0 = bj * 128 + tx * 8;
#pragma unroll
    for (int r = 0; r < 8; r++) {
        *(float4*)&gp[(size_t)(r0 + r) * R_ + c0]     = make_float4(acc[r][0], acc[r][1], acc[r][2], acc[r][3]);
        *(float4*)&gp[(size_t)(r0 + r) * R_ + c0 + 4] = make_float4(acc[r][4], acc[r][5], acc[r][6], acc[r][7]);
    }
}

// ---------------- sigma = (D^T D - Q * sum_c mu_c mu_c^T)/M + 1e-4 I (full symmetric) ----------------
__global__ void sigma_kernel() {
    int gid = blockIdx.x * 256 + threadIdx.x;   // 4096 blocks
    int i = gid >> 10, j = gid & 1023;
    size_t lo = (j <= i) ? ((size_t)i * R_ + j) : ((size_t)j * R_ + i);
    float s = 0.f;
#pragma unroll
    for (int z = 0; z < KSPLIT; z++) s += g_Gp[z][lo];
    float corr = 0.f;
#pragma unroll
    for (int c = 0; c < C_; c++) corr += g_mu[c * R_ + i] * g_mu[c * R_ + j];
    float v = (s - (float)Q_ * corr) * (1.f / (float)M_);
    if (i == j) v += 1e-4f;
    g_S[(size_t)i * R_ + j] = v;
}

// ---------------- blocked Cholesky, panel B=64 ----------------
__global__ void potf2_kernel(int p) {
    __shared__ float s[64][65];
    int o = p * 64, tid = threadIdx.x;          // 128 threads
    for (int idx = tid; idx < 4096; idx += 128) {
        int i = idx >> 6, j = idx & 63;
        s[i][j] = (j <= i) ? g_S[(size_t)(o + i) * R_ + o + j] : 0.f;
    }
    __syncthreads();
    for (int k = 0; k < 64; k++) {
        if (tid == 0) s[k][k] = sqrtf(s[k][k]);
        __syncthreads();
        float d = s[k][k];
        for (int i = k + 1 + tid; i < 64; i += 128) s[i][k] /= d;
        __syncthreads();
        int n = 63 - k;
        for (int idx = tid; idx < n * n; idx += 128) {
            int i = k + 1 + idx / n, j = k + 1 + idx % n;
            if (j <= i) s[i][j] -= s[i][k] * s[j][k];
        }
        __syncthreads();
    }
    for (int idx = tid; idx < 4096; idx += 128) {
        int i = idx >> 6, j = idx & 63;
        if (j <= i) g_S[(size_t)(o + i) * R_ + o + j] = s[i][j];
    }
}

__global__ void chol_trsm_kernel(int p) {
    int o = p * 64, o2 = o + 64;
    __shared__ float L11[64][65];
    __shared__ float invd[64];
    int tid = threadIdx.x;                      // 256 threads
    for (int idx = tid; idx < 4096; idx += 256) {
        int i = idx >> 6, j = idx & 63;
        L11[i][j] = (j <= i) ? g_S[(size_t)(o + i) * R_ + o + j] : 0.f;
    }
    __syncthreads();
    if (tid < 64) invd[tid] = 1.f / L11[tid][tid];
    __syncthreads();
    int r = o2 + blockIdx.x * 256 + tid;
    if (r < R_) {
        float row[64];
        float* g = g_S + (size_t)r * R_ + o;
#pragma unroll
        for (int j = 0; j < 64; j++) row[j] = g[j];
#pragma unroll
        for (int j = 0; j < 64; j++) {
            float a = row[j];
#pragma unroll
            for (int k = 0; k < j; k++) a -= row[k] * L11[j][k];
            row[j] = a * invd[j];
        }
#pragma unroll
        for (int j = 0; j < 64; j++) g[j] = row[j];
    }
}

__global__ void chol_syrk_kernel(int p) {
    int o = p * 64, o2 = o + 64;
    int t = blockIdx.x, bi = 0;
    while ((bi + 1) * (bi + 2) / 2 <= t) bi++;
    int bj = t - bi * (bi + 1) / 2;
    __shared__ float As[64][65];
    __shared__ float Bs[64][65];
    int tid = threadIdx.x;                      // 256 threads
    for (int idx = tid; idx < 4096; idx += 256) {
        int i = idx >> 6, j = idx & 63;
        As[i][j] = g_S[(size_t)(o2 + bi * 64 + i) * R_ + o + j];
        Bs[i][j] = g_S[(size_t)(o2 + bj * 64 + i) * R_ + o + j];
    }
    __syncthreads();
    int tx = tid & 15, ty = tid >> 4;
    float acc[4][4];
#pragma unroll
    for (int r = 0; r < 4; r++)
#pragma unroll
        for (int c = 0; c < 4; c++) acc[r][c] = 0.f;
#pragma unroll 8
    for (int k = 0; k < 64; k++) {
        float a[4], b[4];
#pragma unroll
        for (int r = 0; r < 4; r++) a[r] = As[ty * 4 + r][k];
#pragma unroll
        for (int c = 0; c < 4; c++) b[c] = Bs[tx * 4 + c][k];
#pragma unroll
        for (int r = 0; r < 4; r++)
#pragma unroll
            for (int c = 0; c < 4; c++) acc[r][c] = fmaf(a[r], b[c], acc[r][c]);
    }
#pragma unroll
    for (int r = 0; r < 4; r++)
#pragma unroll
        for (int c = 0; c < 4; c++)
            g_S[(size_t)(o2 + bi * 64 + ty * 4 + r) * R_ + o2 + bj * 64 + tx * 4 + c] -= acc[r][c];
}

// ---------------- ||eps||^2 per row + per-class argmax (first-index tie-break) ----------------
__global__ void sq_kernel(const float* __restrict__ eps) {
    int row = blockIdx.x * 8 + (threadIdx.x >> 5);   // 12500 blocks x 8 warps
    int lane = threadIdx.x & 31;
    const float4* p = (const float4*)(eps + (size_t)row * R_);
    float ss = 0.f;
#pragma unroll
    for (int it = 0; it < 8; it++) {
        float4 v = p[lane + it * 32];
        ss = fmaf(v.x, v.x, fmaf(v.y, v.y, fmaf(v.z, v.z, fmaf(v.w, v.w, ss))));
    }
#pragma unroll
    for (int o = 16; o; o >>= 1) ss += __shfl_xor_sync(0xffffffffu, ss, o);
    if (lane == 0) {
        int c = row / S_;
        unsigned s = (unsigned)(row - c * S_);
        unsigned long long key = ((unsigned long long)__float_as_uint(ss) << 32)
                               | (unsigned long long)(0xFFFFFFFFu - s);
        atomicMax(&g_amax[c], key);
    }
}

__global__ void gather_kernel(const float* __restrict__ eps) {
    int c = blockIdx.x;
    unsigned s = 0xFFFFFFFFu - (unsigned)(g_amax[c] & 0xFFFFFFFFull);
    const float4* src = (const float4*)(eps + ((size_t)c * S_ + s) * R_);
    ((float4*)(g_eps_sel + c * R_))[threadIdx.x] = src[threadIdx.x];
}

// ---------------- vos = mu + L @ eps_sel ----------------
__global__ void vos_kernel() {
    int c = blockIdx.x, tid = threadIdx.x;      // 10 blocks x 256
    __shared__ float e[R_];
    for (int i = tid; i < R_; i += 256) e[i] = g_eps_sel[c * R_ + i];
    __syncthreads();
    int w = tid >> 5, lane = tid & 31;
    for (int i = w; i < R_; i += 8) {
        const float* Lr = g_S + (size_t)i * R_;
        float s = 0.f;
        for (int j = lane; j <= i; j += 32) s += Lr[j] * e[j];
#pragma unroll
        for (int o = 16; o; o >>= 1) s += __shfl_xor_sync(0xffffffffu, s, o);
        if (lane == 0) g_vos[c * R_ + i] = g_mu[c * R_ + i] + s;
    }
}

// ---------------- scores + focal (cls path) ----------------
__global__ void scores_cls_kernel(const float* __restrict__ X, const float* __restrict__ W,
                                  const float* __restrict__ b, const int* __restrict__ labels) {
    __shared__ float red[C_][8];
    __shared__ float srow[C_];
    int row = blockIdx.x, tid = threadIdx.x;    // 512 blocks x 256
    float acc[C_];
#pragma unroll
    for (int c = 0; c < C_; c++) acc[c] = 0.f;
    const float* x = X + (size_t)row * R_;
    for (int r = tid; r < R_; r += 256) {
        float xv = x[r];
#pragma unroll
        for (int c = 0; c < C_; c++) acc[c] = fmaf(xv, W[c * R_ + r], acc[c]);
    }
#pragma unroll
    for (int c = 0; c < C_; c++) {
        float v = acc[c];
#pragma unroll
        for (int o = 16; o; o >>= 1) v += __shfl_xor_sync(0xffffffffu, v, o);
        acc[c] = v;
    }
    int w = tid >> 5, lane = tid & 31;
    if (lane == 0)
#pragma unroll
        for (int c = 0; c < C_; c++) red[c][w] = acc[c];
    __syncthreads();
    if (tid < C_) {
        float s = red[tid][0];
#pragma unroll
        for (int ww = 1; ww < 8; ww++) s += red[tid][ww];
        s += b[tid];
        g_scores[row * C_ + tid] = s;
        srow[tid] = s;
    }
    __syncthreads();
    if (tid == 0) {
        int lab = labels[row];
        float fs = 0.f;
#pragma unroll
        for (int c = 0; c < C_; c++) {
            float xv = srow[c];
            float tt = (c == lab) ? 1.f : 0.f;
            float ce = fmaxf(xv, 0.f) - xv * tt + log1pf(expf(-fabsf(xv)));
            float pp = 1.f / (1.f + expf(-xv));
            float pt = pp * tt + (1.f - pp) * (1.f - tt);
            float at = 0.25f * tt + 0.75f * (1.f - tt);
            float om = 1.f - pt;
            fs += at * ce * om * om;
        }
        g_focal[row] = fs;
    }
}

// ---------------- scores_vos = vos @ W^T + b ----------------
__global__ void scores_vos_kernel(const float* __restrict__ W, const float* __restrict__ b) {
    __shared__ float red[C_][8];
    int row = blockIdx.x, tid = threadIdx.x;    // 10 blocks x 256
    float acc[C_];
#pragma unroll
    for (int c = 0; c < C_; c++) acc[c] = 0.f;
    const float* x = g_vos + (size_t)row * R_;
    for (int r = tid; r < R_; r += 256) {
        float xv = x[r];
#pragma unroll
        for (int c = 0; c < C_; c++) acc[c] = fmaf(xv, W[c * R_ + r], acc[c]);
    }
#pragma unroll
    for (int c = 0; c < C_; c++) {
        float v = acc[c];
#pragma unroll
        for (int o = 16; o; o >>= 1) v += __shfl_xor_sync(0xffffffffu, v, o);
        acc[c] = v;
    }
    int w = tid >> 5, lane = tid & 31;
    if (lane == 0)
#pragma unroll
        for (int c = 0; c < C_; c++) red[c][w] = acc[c];
    __syncthreads();
    if (tid < C_) {
        float s = red[tid][0];
#pragma unroll
        for (int ww = 1; ww < 8; ww++) s += red[tid][ww];
        g_scores_vos[row * C_ + tid] = s + b[tid];
    }
}

// ---------------- energy -> MLP -> BCE, plus focal reduction ----------------
__global__ void final_kernel(const float* __restrict__ w_e, const float* __restrict__ W1,
                             const float* __restrict__ b1, const float* __restrict__ W2,
                             const float* __restrict__ b2, float* __restrict__ out) {
    __shared__ float we[C_];
    __shared__ float bce[544];
    __shared__ float foc[N_];
    int tid = threadIdx.x;                      // 544 threads
    if (tid < C_) we[tid] = fmaxf(w_e[tid], 0.f);
    for (int i = tid; i < N_; i += 544) foc[i] = g_focal[i];
    __syncthreads();
    float v = 0.f;
    if (tid < N_ + C_) {
        const float* row = (tid < N_) ? (g_scores + tid * C_) : (g_scores_vos + (tid - N_) * C_);
        float m = row[0];
#pragma unroll
        for (int c = 1; c < C_; c++) m = fmaxf(m, row[c]);
        float ssum = 0.f;
#pragma unroll
        for (int c = 0; c < C_; c++) ssum += expf(row[c] - m) * we[c];
        float e = m + logf(ssum);
        float lg = 0.f;
        for (int j = 0; j < 512; j++) lg = fmaf(fmaxf(fmaf(e, W1[j], b1[j]), 0.f), W2[j], lg);
        lg += b2[0];
        float y = (tid < N_) ? 1.f : 0.f;
        v = fmaxf(lg, 0.f) - lg * y + log1pf(expf(-fabsf(lg)));
    }
    bce[tid] = v;
    __syncthreads();
    if (tid == 0) {
        float bs = 0.f;
        for (int i = 0; i < N_ + C_; i++) bs += bce[i];
        float fsum = 0.f;
        for (int i = 0; i < N_; i++) fsum += foc[i];
        out[0] = fsum / (float)N_;
        out[1] = 0.1f * bs / (float)(N_ + C_);
    }
}

// ---------------- launch ----------------
extern "C" void kernel_launch(void* const* d_in, const int* in_sizes, int n_in,
                              void* d_out, int out_size) {
    const float* box     = (const float*)d_in[0];
    const int*   labels  = (const int*)d_in[1];
    const float* id_data = (const float*)d_in[2];
    // d_in[3] = id_data_counter (all full -> roll path; not needed on device)
    const float* W_pred  = (const float*)d_in[4];
    const float* b_pred  = (const float*)d_in[5];
    const float* w_e     = (const float*)d_in[6];
    const float* dW1     = (const float*)d_in[7];
    const float* db1     = (const float*)d_in[8];
    const float* dW2     = (const float*)d_in[9];
    const float* db2     = (const float*)d_in[10];
    const float* eps     = (const float*)d_in[11];
    float* out = (float*)d_out;
    (void)in_sizes; (void)n_in; (void)out_size;

    order_kernel<<<1, 512>>>(labels);
    sq_kernel<<<(C_ * S_) / 8, 256>>>(eps);
    matD_kernel<<<M_, 256>>>(id_data, box);
    mu_kernel<<<(C_ * R_) / 256, 256>>>();
    syrk_kernel<<<dim3(36, KSPLIT), 256>>>();
    sigma_kernel<<<(R_ * R_) / 256, 256>>>();
    for (int p = 0; p < 16; p++) {
        potf2_kernel<<<1, 128>>>(p);
        int nr = R_ - (p + 1) * 64;
        if (nr > 0) {
            chol_trsm_kernel<<<(nr + 255) / 256, 256>>>(p);
            int nt = nr / 64;
            chol_syrk_kernel<<<nt * (nt + 1) / 2, 256>>>(p);
        }
    }
    gather_kernel<<<C_, 256>>>(eps);
    vos_kernel<<<C_, 256>>>();
    scores_cls_kernel<<<N_, 256>>>(box, W_pred, b_pred, labels);
    scores_vos_kernel<<<C_, 256>>>(W_pred, b_pred);
    final_kernel<<<1, 544>>>(w_e, dW1, db1, dW2, db2, out);
}

// round 12
// speedup vs baseline: 1.0975x; 1.0975x over previous
#include <cuda_runtime.h>
#include <math.h>

#define C_ 10
#define Q_ 1000
#define R_ 1024
#define N_ 512
#define S_ 10000
#define M_ 10000          // C_*Q_
#define KSPLIT 8
#define CHUNK 1250        // M_/KSPLIT
#define MCH 40            // mu chunk rows
#define NMCH 250          // M_/MCH
#define SSTR 136          // SMEM row stride (floats): 136 % 32 == 8 -> conflict-free frags

// ---------------- static device scratch (no allocations allowed) ----------------
static __device__ float g_D[M_ * R_];                  // updated queues, 40.96 MB
static __device__ float g_Gp[KSPLIT][R_ * R_];         // SYRK partials (lower), 33.5 MB
static __device__ float g_S[R_ * R_];                  // sigma (lower) -> L in place
static __device__ float g_mup[NMCH * R_];              // mu partials
static __device__ float g_mu[C_ * R_];
static __device__ float g_scores[N_ * C_];
static __device__ float g_scores_vos[C_ * C_];
static __device__ float g_eps_sel[C_ * R_];
static __device__ float g_vos[C_ * R_];
static __device__ float g_focal[N_];
static __device__ int   g_order[C_ * N_];
static __device__ int   g_cnt[C_];
static __device__ unsigned long long g_amax[C_];

// ---------------- per-class sample ordering (faithful sequential queue) ----------------
__global__ void order_kernel(const int* __restrict__ labels) {
    __shared__ int labs[N_];
    int tid = threadIdx.x;                   // 512 threads
    labs[tid] = labels[tid];
    if (tid < C_) { g_cnt[tid] = 0; g_amax[tid] = 0ull; }
    __syncthreads();
    int lab = labs[tid];
    int pos = 0;
    for (int j = 0; j < tid; j++) pos += (labs[j] == lab) ? 1 : 0;
    g_order[lab * N_ + pos] = tid;
    atomicAdd(&g_cnt[lab], 1);
}

// ---------------- materialize updated queue data D ----------------
__global__ void matD_kernel(const float* __restrict__ id_data, const float* __restrict__ box) {
    int row = blockIdx.x;                    // 0..9999
    int c = row / Q_, q = row - c * Q_;
    int k = g_cnt[c];
    const float* src;
    if (q < Q_ - k) src = id_data + (size_t)(c * Q_ + q + k) * R_;
    else            src = box + (size_t)g_order[c * N_ + q - (Q_ - k)] * R_;
    ((float4*)(g_D + (size_t)row * R_))[threadIdx.x] = ((const float4*)src)[threadIdx.x];
}

// ---------------- per-class mean: coalesced chunk partials + reduce ----------------
__global__ void mu_part_kernel() {                     // grid 250, 256 thr
    int z = blockIdx.x;
    const float4* base = (const float4*)(g_D + (size_t)z * MCH * R_);
    float4 s = make_float4(0.f, 0.f, 0.f, 0.f);
    for (int q = 0; q < MCH; q++) {
        float4 v = base[q * (R_ / 4) + threadIdx.x];
        s.x += v.x; s.y += v.y; s.z += v.z; s.w += v.w;
    }
    ((float4*)g_mup)[z * (R_ / 4) + threadIdx.x] = s;
}
__global__ void mu_reduce_kernel() {                   // grid 40, 256 thr
    int gid = blockIdx.x * 256 + threadIdx.x;          // 10240 = C_*R_
    int c = gid >> 10, r = gid & 1023;
    float s = 0.f;
#pragma unroll
    for (int z = 0; z < NMCH / C_; z++) s += g_mup[(c * (NMCH / C_) + z) * R_ + r];
    g_mu[gid] = s * (1.f / (float)Q_);
}

// ---------------- tf32 tensor-core SYRK: Gp[z] = D_chunk^T D_chunk (lower 128x128 tiles) ----------------
__device__ __forceinline__ unsigned f2tf(float x) {
    unsigned r; asm("cvt.rna.tf32.f32 %0, %1;" : "=r"(r) : "f"(x)); return r;
}
__device__ __forceinline__ void mma_tf32(float* d, const unsigned* a, const unsigned* b) {
    asm volatile(
        "mma.sync.aligned.m16n8k8.row.col.f32.tf32.tf32.f32 "
        "{%0,%1,%2,%3}, {%4,%5,%6,%7}, {%8,%9}, {%0,%1,%2,%3};\n"
        : "+f"(d[0]), "+f"(d[1]), "+f"(d[2]), "+f"(d[3])
        : "r"(a[0]), "r"(a[1]), "r"(a[2]), "r"(a[3]), "r"(b[0]), "r"(b[1]));
}

__global__ __launch_bounds__(256, 2) void syrk_kernel() {
    int t = blockIdx.x;
    int bi = 0;
    while ((bi + 1) * (bi + 2) / 2 <= t) bi++;
    int bj = t - bi * (bi + 1) / 2;

    __shared__ unsigned SA[32 * SSTR];
    __shared__ unsigned SB[32 * SSTR];

    int tid = threadIdx.x;
    int wid = tid >> 5, lane = tid & 31;
    int wy = wid & 1, wx = wid >> 1;         // warp tile: rows wy*64, cols wx*32
    int g = lane >> 2, tg = lane & 3;

    int m0 = blockIdx.y * CHUNK, m1 = m0 + CHUNK;

    float acc[4][4][4];
#pragma unroll
    for (int mf = 0; mf < 4; mf++)
#pragma unroll
        for (int nf = 0; nf < 4; nf++)
#pragma unroll
            for (int q = 0; q < 4; q++) acc[mf][nf][q] = 0.f;

    int lr = tid >> 3;                       // load row 0..31
    int lc = tid & 7;                        // load col-quarter base

    for (int mb = m0; mb < m1; mb += 32) {
        {
            int m = mb + lr;
            bool v = m < m1;
            const float4* rpA = (const float4*)(g_D + (size_t)m * R_ + bi * 128);
            const float4* rpB = (const float4*)(g_D + (size_t)m * R_ + bj * 128);
            float4 z4 = make_float4(0.f, 0.f, 0.f, 0.f);
#pragma unroll
            for (int i = 0; i < 4; i++) {
                int c4 = lc + 8 * i;
                float4 a = v ? rpA[c4] : z4;
                float4 b = v ? rpB[c4] : z4;
                *(uint4*)&SA[lr * SSTR + c4 * 4] = make_uint4(f2tf(a.x), f2tf(a.y), f2tf(a.z), f2tf(a.w));
                *(uint4*)&SB[lr * SSTR + c4 * 4] = make_uint4(f2tf(b.x), f2tf(b.y), f2tf(b.z), f2tf(b.w));
            }
        }
        __syncthreads();
#pragma unroll
        for (int ks = 0; ks < 4; ks++) {
            int k0 = ks * 8;
            unsigned af[4][4], bf[4][2];
#pragma unroll
            for (int mf = 0; mf < 4; mf++) {
                int r0 = wy * 64 + mf * 16;
                af[mf][0] = SA[(k0 + tg) * SSTR + r0 + g];
                af[mf][1] = SA[(k0 + tg) * SSTR + r0 + g + 8];
                af[mf][2] = SA[(k0 + tg + 4) * SSTR + r0 + g];
                af[mf][3] = SA[(k0 + tg + 4) * SSTR + r0 + g + 8];
            }
#pragma unroll
            for (int nf = 0; nf < 4; nf++) {
                int c0 = wx * 32 + nf * 8;
                bf[nf][0] = SB[(k0 + tg) * SSTR + c0 + g];
                bf[nf][1] = SB[(k0 + tg + 4) * SSTR + c0 + g];
            }
#pragma unroll
            for (int mf = 0; mf < 4; mf++)
#pragma unroll
                for (int nf = 0; nf < 4; nf++)
                    mma_tf32(acc[mf][nf], af[mf], bf[nf]);
        }
        __syncthreads();
    }
    float* gp = g_Gp[blockIdx.y];
#pragma unroll
    for (int mf = 0; mf < 4; mf++) {
        int r0 = bi * 128 + wy * 64 + mf * 16 + g;
#pragma unroll
        for (int nf = 0; nf < 4; nf++) {
            int c0 = bj * 128 + wx * 32 + nf * 8 + 2 * tg;
            *(float2*)&gp[(size_t)r0 * R_ + c0]       = make_float2(acc[mf][nf][0], acc[mf][nf][1]);
            *(float2*)&gp[(size_t)(r0 + 8) * R_ + c0] = make_float2(acc[mf][nf][2], acc[mf][nf][3]);
        }
    }
}

// ---------------- sigma (lower only) = (sum Gp - Q*sum_c mu mu^T)/M + 1e-4 I ----------------
__global__ void sigma_kernel() {
    int gid = blockIdx.x * 256 + threadIdx.x;   // 4096 blocks
    int i = gid >> 10, j = gid & 1023;
    if (j > i) return;
    size_t lo = (size_t)i * R_ + j;
    float s = 0.f;
#pragma unroll
    for (int z = 0; z < KSPLIT; z++) s += g_Gp[z][lo];
    float corr = 0.f;
#pragma unroll
    for (int c = 0; c < C_; c++) corr += g_mu[c * R_ + i] * g_mu[c * R_ + j];
    float v = (s - (float)Q_ * corr) * (1.f / (float)M_);
    if (i == j) v += 1e-4f;
    g_S[lo] = v;
}

// ---------------- blocked Cholesky, panel B=64 ----------------
__global__ void potf2_kernel(int p) {           // 64 threads
    __shared__ float s[64][65];
    int o = p * 64, tid = threadIdx.x;
    for (int idx = tid; idx < 4096; idx += 64) {
        int i = idx >> 6, j = idx & 63;
        s[i][j] = (j <= i) ? g_S[(size_t)(o + i) * R_ + o + j] : 0.f;
    }
    __syncthreads();
    for (int k = 0; k < 64; k++) {
        if (tid == k) s[k][k] = sqrtf(s[k][k]);
        __syncthreads();
        if (tid > k) s[tid][k] /= s[k][k];
        __syncthreads();
        if (tid > k) {
            float lik = s[tid][k];
            for (int j = k + 1; j <= tid; j++) s[tid][j] -= lik * s[j][k];
        }
        __syncthreads();
    }
    for (int idx = tid; idx < 4096; idx += 64) {
        int i = idx >> 6, j = idx & 63;
        if (j <= i) g_S[(size_t)(o + i) * R_ + o + j] = s[i][j];
    }
}

__global__ void chol_trsm_kernel(int p) {
    int o = p * 64, o2 = o + 64;
    __shared__ float L11[64][65];
    __shared__ float invd[64];
    int tid = threadIdx.x;                      // 256 threads
    for (int idx = tid; idx < 4096; idx += 256) {
        int i = idx >> 6, j = idx & 63;
        L11[i][j] = (j <= i) ? g_S[(size_t)(o + i) * R_ + o + j] : 0.f;
    }
    __syncthreads();
    if (tid < 64) invd[tid] = 1.f / L11[tid][tid];
    __syncthreads();
    int r = o2 + blockIdx.x * 256 + tid;
    if (r < R_) {
        float row[64];
        float* g = g_S + (size_t)r * R_ + o;
#pragma unroll
        for (int j = 0; j < 64; j++) row[j] = g[j];
#pragma unroll
        for (int j = 0; j < 64; j++) {
            float a = row[j];
#pragma unroll
            for (int k = 0; k < j; k++) a -= row[k] * L11[j][k];
            row[j] = a * invd[j];
        }
#pragma unroll
        for (int j = 0; j < 64; j++) g[j] = row[j];
    }
}

__global__ void chol_syrk_kernel(int p) {
    int o = p * 64, o2 = o + 64;
    int t = blockIdx.x, bi = 0;
    while ((bi + 1) * (bi + 2) / 2 <= t) bi++;
    int bj = t - bi * (bi + 1) / 2;
    __shared__ float As[64][65];
    __shared__ float Bs[64][65];
    int tid = threadIdx.x;                      // 256 threads
    for (int idx = tid; idx < 4096; idx += 256) {
        int i = idx >> 6, j = idx & 63;
        As[i][j] = g_S[(size_t)(o2 + bi * 64 + i) * R_ + o + j];
        Bs[i][j] = g_S[(size_t)(o2 + bj * 64 + i) * R_ + o + j];
    }
    __syncthreads();
    int tx = tid & 15, ty = tid >> 4;
    float acc[4][4];
#pragma unroll
    for (int r = 0; r < 4; r++)
#pragma unroll
        for (int c = 0; c < 4; c++) acc[r][c] = 0.f;
#pragma unroll 8
    for (int k = 0; k < 64; k++) {
        float a[4], b[4];
#pragma unroll
        for (int r = 0; r < 4; r++) a[r] = As[ty * 4 + r][k];
#pragma unroll
        for (int c = 0; c < 4; c++) b[c] = Bs[tx * 4 + c][k];
#pragma unroll
        for (int r = 0; r < 4; r++)
#pragma unroll
            for (int c = 0; c < 4; c++) acc[r][c] = fmaf(a[r], b[c], acc[r][c]);
    }
#pragma unroll
    for (int r = 0; r < 4; r++)
#pragma unroll
        for (int c = 0; c < 4; c++)
            g_S[(size_t)(o2 + bi * 64 + ty * 4 + r) * R_ + o2 + bj * 64 + tx * 4 + c] -= acc[r][c];
}

// ---------------- ||eps||^2 per row + per-class argmax (first-index tie-break) ----------------
__global__ void sq_kernel(const float* __restrict__ eps) {
    int row = blockIdx.x * 8 + (threadIdx.x >> 5);   // 12500 blocks x 8 warps
    int lane = threadIdx.x & 31;
    const float4* p = (const float4*)(eps + (size_t)row * R_);
    float ss = 0.f;
#pragma unroll
    for (int it = 0; it < 8; it++) {
        float4 v = p[lane + it * 32];
        ss = fmaf(v.x, v.x, fmaf(v.y, v.y, fmaf(v.z, v.z, fmaf(v.w, v.w, ss))));
    }
#pragma unroll
    for (int o = 16; o; o >>= 1) ss += __shfl_xor_sync(0xffffffffu, ss, o);
    if (lane == 0) {
        int c = row / S_;
        unsigned s = (unsigned)(row - c * S_);
        unsigned long long key = ((unsigned long long)__float_as_uint(ss) << 32)
                               | (unsigned long long)(0xFFFFFFFFu - s);
        atomicMax(&g_amax[c], key);
    }
}

__global__ void gather_kernel(const float* __restrict__ eps) {
    int c = blockIdx.x;
    unsigned s = 0xFFFFFFFFu - (unsigned)(g_amax[c] & 0xFFFFFFFFull);
    const float4* src = (const float4*)(eps + ((size_t)c * S_ + s) * R_);
    ((float4*)(g_eps_sel + c * R_))[threadIdx.x] = src[threadIdx.x];
}

// ---------------- vos = mu + L @ eps_sel : one pass over L, all 10 classes ----------------
__global__ void vos_kernel() {                  // grid 16 blocks x 256 thr, 64 rows/block
    __shared__ float e[C_][R_];                 // 40 KB
    int tid = threadIdx.x;
    for (int i = tid; i < C_ * R_; i += 256) ((float*)e)[i] = g_eps_sel[i];
    __syncthreads();
    int w = tid >> 5, lane = tid & 31;
    for (int rr = 0; rr < 8; rr++) {
        int i = blockIdx.x * 64 + rr * 8 + w;
        const float* Lr = g_S + (size_t)i * R_;
        float p[C_];
#pragma unroll
        for (int c = 0; c < C_; c++) p[c] = 0.f;
        for (int j = lane; j <= i; j += 32) {
            float Lv = Lr[j];
#pragma unroll
            for (int c = 0; c < C_; c++) p[c] = fmaf(Lv, e[c][j], p[c]);
        }
#pragma unroll
        for (int c = 0; c < C_; c++) {
            float v = p[c];
#pragma unroll
            for (int o = 16; o; o >>= 1) v += __shfl_xor_sync(0xffffffffu, v, o);
            if (lane == 0) g_vos[c * R_ + i] = g_mu[c * R_ + i] + v;
        }
    }
}

// ---------------- scores + focal (cls path) ----------------
__global__ void scores_cls_kernel(const float* __restrict__ X, const float* __restrict__ W,
                                  const float* __restrict__ b, const int* __restrict__ labels) {
    __shared__ float red[C_][8];
    __shared__ float srow[C_];
    int row = blockIdx.x, tid = threadIdx.x;    // 512 blocks x 256
    float acc[C_];
#pragma unroll
    for (int c = 0; c < C_; c++) acc[c] = 0.f;
    const float* x = X + (size_t)row * R_;
    for (int r = tid; r < R_; r += 256) {
        float xv = x[r];
#pragma unroll
        for (int c = 0; c < C_; c++) acc[c] = fmaf(xv, W[c * R_ + r], acc[c]);
    }
#pragma unroll
    for (int c = 0; c < C_; c++) {
        float v = acc[c];
#pragma unroll
        for (int o = 16; o; o >>= 1) v += __shfl_xor_sync(0xffffffffu, v, o);
        acc[c] = v;
    }
    int w = tid >> 5, lane = tid & 31;
    if (lane == 0)
#pragma unroll
        for (int c = 0; c < C_; c++) red[c][w] = acc[c];
    __syncthreads();
    if (tid < C_) {
        float s = red[tid][0];
#pragma unroll
        for (int ww = 1; ww < 8; ww++) s += red[tid][ww];
        s += b[tid];
        g_scores[row * C_ + tid] = s;
        srow[tid] = s;
    }
    __syncthreads();
    if (tid == 0) {
        int lab = labels[row];
        float fs = 0.f;
#pragma unroll
        for (int c = 0; c < C_; c++) {
            float xv = srow[c];
            float tt = (c == lab) ? 1.f : 0.f;
            float ce = fmaxf(xv, 0.f) - xv * tt + log1pf(expf(-fabsf(xv)));
            float pp = 1.f / (1.f + expf(-xv));
            float pt = pp * tt + (1.f - pp) * (1.f - tt);
            float at = 0.25f * tt + 0.75f * (1.f - tt);
            float om = 1.f - pt;
            fs += at * ce * om * om;
        }
        g_focal[row] = fs;
    }
}

// ---------------- scores_vos = vos @ W^T + b ----------------
__global__ void scores_vos_kernel(const float* __restrict__ W, const float* __restrict__ b) {
    __shared__ float red[C_][8];
    int row = blockIdx.x, tid = threadIdx.x;    // 10 blocks x 256
    float acc[C_];
#pragma unroll
    for (int c = 0; c < C_; c++) acc[c] = 0.f;
    const float* x = g_vos + (size_t)row * R_;
    for (int r = tid; r < R_; r += 256) {
        float xv = x[r];
#pragma unroll
        for (int c = 0; c < C_; c++) acc[c] = fmaf(xv, W[c * R_ + r], acc[c]);
    }
#pragma unroll
    for (int c = 0; c < C_; c++) {
        float v = acc[c];
#pragma unroll
        for (int o = 16; o; o >>= 1) v += __shfl_xor_sync(0xffffffffu, v, o);
        acc[c] = v;
    }
    int w = tid >> 5, lane = tid & 31;
    if (lane == 0)
#pragma unroll
        for (int c = 0; c < C_; c++) red[c][w] = acc[c];
    __syncthreads();
    if (tid < C_) {
        float s = red[tid][0];
#pragma unroll
        for (int ww = 1; ww < 8; ww++) s += red[tid][ww];
        g_scores_vos[row * C_ + tid] = s + b[tid];
    }
}

// ---------------- energy -> MLP -> BCE, plus focal reduction ----------------
__global__ void final_kernel(const float* __restrict__ w_e, const float* __restrict__ W1,
                             const float* __restrict__ b1, const float* __restrict__ W2,
                             const float* __restrict__ b2, float* __restrict__ out) {
    __shared__ float we[C_];
    __shared__ float bce[544];
    __shared__ float foc[N_];
    int tid = threadIdx.x;                      // 544 threads
    if (tid < C_) we[tid] = fmaxf(w_e[tid], 0.f);
    for (int i = tid; i < N_; i += 544) foc[i] = g_focal[i];
    __syncthreads();
    float v = 0.f;
    if (tid < N_ + C_) {
        const float* row = (tid < N_) ? (g_scores + tid * C_) : (g_scores_vos + (tid - N_) * C_);
        float m = row[0];
#pragma unroll
        for (int c = 1; c < C_; c++) m = fmaxf(m, row[c]);
        float ssum = 0.f;
#pragma unroll
        for (int c = 0; c < C_; c++) ssum += expf(row[c] - m) * we[c];
        float e = m + logf(ssum);
        float lg = 0.f;
        for (int j = 0; j < 512; j++) lg = fmaf(fmaxf(fmaf(e, W1[j], b1[j]), 0.f), W2[j], lg);
        lg += b2[0];
        float y = (tid < N_) ? 1.f : 0.f;
        v = fmaxf(lg, 0.f) - lg * y + log1pf(expf(-fabsf(lg)));
    }
    bce[tid] = v;
    __syncthreads();
    if (tid == 0) {
        float bs = 0.f;
        for (int i = 0; i < N_ + C_; i++) bs += bce[i];
        float fsum = 0.f;
        for (int i = 0; i < N_; i++) fsum += foc[i];
        out[0] = fsum / (float)N_;
        out[1] = 0.1f * bs / (float)(N_ + C_);
    }
}

// ---------------- launch ----------------
extern "C" void kernel_launch(void* const* d_in, const int* in_sizes, int n_in,
                              void* d_out, int out_size) {
    const float* box     = (const float*)d_in[0];
    const int*   labels  = (const int*)d_in[1];
    const float* id_data = (const float*)d_in[2];
    const float* W_pred  = (const float*)d_in[4];
    const float* b_pred  = (const float*)d_in[5];
    const float* w_e     = (const float*)d_in[6];
    const float* dW1     = (const float*)d_in[7];
    const float* db1     = (const float*)d_in[8];
    const float* dW2     = (const float*)d_in[9];
    const float* db2     = (const float*)d_in[10];
    const float* eps     = (const float*)d_in[11];
    float* out = (float*)d_out;
    (void)in_sizes; (void)n_in; (void)out_size;

    order_kernel<<<1, 512>>>(labels);
    sq_kernel<<<(C_ * S_) / 8, 256>>>(eps);
    matD_kernel<<<M_, 256>>>(id_data, box);
    mu_part_kernel<<<NMCH, 256>>>();
    mu_reduce_kernel<<<(C_ * R_) / 256, 256>>>();
    syrk_kernel<<<dim3(36, KSPLIT), 256>>>();
    sigma_kernel<<<(R_ * R_) / 256, 256>>>();
    for (int p = 0; p < 16; p++) {
        potf2_kernel<<<1, 64>>>(p);
        int nr = R_ - (p + 1) * 64;
        if (nr > 0) {
            chol_trsm_kernel<<<(nr + 255) / 256, 256>>>(p);
            int nt = nr / 64;
            chol_syrk_kernel<<<nt * (nt + 1) / 2, 256>>>(p);
        }
    }
    gather_kernel<<<C_, 256>>>(eps);
    vos_kernel<<<16, 256>>>();
    scores_cls_kernel<<<N_, 256>>>(box, W_pred, b_pred, labels);
    scores_vos_kernel<<<C_, 256>>>(W_pred, b_pred);
    final_kernel<<<1, 544>>>(w_e, dW1, db1, dW2, db2, out);
}

// round 13
// speedup vs baseline: 1.4618x; 1.3319x over previous
#include <cuda_runtime.h>
#include <math.h>

#define C_ 10
#define Q_ 1000
#define R_ 1024
#define N_ 512
#define S_ 10000
#define M_ 10000          // C_*Q_
#define MP 10240          // padded rows (zero-filled) -> 8 chunks x 1280, 40 steps of 32
#define KSPLIT 8
#define CHUNKP 1280       // MP/KSPLIT
#define MCH 40            // mu chunk rows
#define NMCH 250          // M_/MCH
#define SSTR 136          // SMEM row stride (floats): conflict-free frag loads
#define TILEF (32*SSTR)   // floats per tile buffer
#define SYRK_SMEM (4*TILEF*4)   // 2 bufs x (A+B) = 69632 bytes
#define CHB 64            // persistent-Cholesky blocks

// ---------------- static device scratch (no allocations allowed) ----------------
static __device__ float g_D[MP * R_];                  // updated queues (padded), 41.9 MB
static __device__ float g_Gp[KSPLIT][R_ * R_];         // SYRK partials (lower), 33.5 MB
static __device__ float g_S[R_ * R_];                  // sigma (lower) -> L in place
static __device__ float g_mup[NMCH * R_];              // mu partials
static __device__ float g_mu[C_ * R_];
static __device__ float g_scores[N_ * C_];
static __device__ float g_scores_vos[C_ * C_];
static __device__ float g_eps_sel[C_ * R_];
static __device__ float g_vos[C_ * R_];
static __device__ float g_focal[N_];
static __device__ int   g_order[C_ * N_];
static __device__ int   g_cnt[C_];
static __device__ unsigned long long g_amax[C_];
static __device__ int   g_bars[64];

// ---------------- per-class sample ordering + replay-state reset ----------------
__global__ void order_kernel(const int* __restrict__ labels) {
    __shared__ int labs[N_];
    int tid = threadIdx.x;                   // 512 threads
    labs[tid] = labels[tid];
    if (tid < C_) { g_cnt[tid] = 0; g_amax[tid] = 0ull; }
    if (tid < 64) g_bars[tid] = 0;
    __syncthreads();
    int lab = labs[tid];
    int pos = 0;
    for (int j = 0; j < tid; j++) pos += (labs[j] == lab) ? 1 : 0;
    g_order[lab * N_ + pos] = tid;
    atomicAdd(&g_cnt[lab], 1);
}

// ---------------- materialize updated queue data D (padded with zeros) ----------------
__global__ void matD_kernel(const float* __restrict__ id_data, const float* __restrict__ box) {
    int row = blockIdx.x;                    // 0..MP-1
    if (row >= M_) {
        ((float4*)(g_D + (size_t)row * R_))[threadIdx.x] = make_float4(0.f, 0.f, 0.f, 0.f);
        return;
    }
    int c = row / Q_, q = row - c * Q_;
    int k = g_cnt[c];
    const float* src;
    if (q < Q_ - k) src = id_data + (size_t)(c * Q_ + q + k) * R_;
    else            src = box + (size_t)g_order[c * N_ + q - (Q_ - k)] * R_;
    ((float4*)(g_D + (size_t)row * R_))[threadIdx.x] = ((const float4*)src)[threadIdx.x];
}

// ---------------- per-class mean: coalesced chunk partials + reduce ----------------
__global__ void mu_part_kernel() {                     // grid 250, 256 thr
    int z = blockIdx.x;
    const float4* base = (const float4*)(g_D + (size_t)z * MCH * R_);
    float4 s = make_float4(0.f, 0.f, 0.f, 0.f);
    for (int q = 0; q < MCH; q++) {
        float4 v = base[q * (R_ / 4) + threadIdx.x];
        s.x += v.x; s.y += v.y; s.z += v.z; s.w += v.w;
    }
    ((float4*)g_mup)[z * (R_ / 4) + threadIdx.x] = s;
}
__global__ void mu_reduce_kernel() {                   // grid 40, 256 thr
    int gid = blockIdx.x * 256 + threadIdx.x;          // 10240 = C_*R_
    int c = gid >> 10, r = gid & 1023;
    float s = 0.f;
#pragma unroll
    for (int z = 0; z < NMCH / C_; z++) s += g_mup[(c * (NMCH / C_) + z) * R_ + r];
    g_mu[gid] = s * (1.f / (float)Q_);
}

// ---------------- tf32 tensor-core SYRK with cp.async double buffering ----------------
__device__ __forceinline__ unsigned f2tf(float x) {
    unsigned r; asm("cvt.rna.tf32.f32 %0, %1;" : "=r"(r) : "f"(x)); return r;
}
__device__ __forceinline__ void mma_tf32(float* d, const unsigned* a, const unsigned* b) {
    asm volatile(
        "mma.sync.aligned.m16n8k8.row.col.f32.tf32.tf32.f32 "
        "{%0,%1,%2,%3}, {%4,%5,%6,%7}, {%8,%9}, {%0,%1,%2,%3};\n"
        : "+f"(d[0]), "+f"(d[1]), "+f"(d[2]), "+f"(d[3])
        : "r"(a[0]), "r"(a[1]), "r"(a[2]), "r"(a[3]), "r"(b[0]), "r"(b[1]));
}
__device__ __forceinline__ void cpasync16(unsigned saddr, const void* g) {
    asm volatile("cp.async.ca.shared.global [%0], [%1], 16;\n" :: "r"(saddr), "l"(g));
}
__device__ __forceinline__ void cp_commit() { asm volatile("cp.async.commit_group;\n"); }
__device__ __forceinline__ void cp_wait0()  { asm volatile("cp.async.wait_group 0;\n"); }

__global__ __launch_bounds__(256, 2) void syrk_kernel() {
    extern __shared__ float smem[];
    int t = blockIdx.x;
    int bi = 0;
    while ((bi + 1) * (bi + 2) / 2 <= t) bi++;
    int bj = t - bi * (bi + 1) / 2;
    bool diag = (bi == bj);

    int tid = threadIdx.x;
    int wid = tid >> 5, lane = tid & 31;
    int wy = wid & 1, wx = wid >> 1;         // warp tile: rows wy*64, cols wx*32
    int g = lane >> 2, tg = lane & 3;
    int lr = tid >> 3;                       // load row 0..31
    int lc = tid & 7;                        // load col-quarter base

    int m0 = blockIdx.y * CHUNKP;

    float acc[4][4][4];
#pragma unroll
    for (int mf = 0; mf < 4; mf++)
#pragma unroll
        for (int nf = 0; nf < 4; nf++)
#pragma unroll
            for (int q = 0; q < 4; q++) acc[mf][nf][q] = 0.f;

    // issue loads for one step into buffer b
    auto issue = [&](int b, int mb) {
        float* SA = smem + b * (2 * TILEF);
        float* SB = SA + TILEF;
        const float* gr = g_D + (size_t)(mb + lr) * R_;
        unsigned sA = (unsigned)__cvta_generic_to_shared(SA + lr * SSTR);
        unsigned sB = (unsigned)__cvta_generic_to_shared(SB + lr * SSTR);
#pragma unroll
        for (int i = 0; i < 4; i++) {
            int c0 = (lc + 8 * i) * 4;       // float offset within 128-col panel
            cpasync16(sA + c0 * 4, gr + bi * 128 + c0);
            if (!diag) cpasync16(sB + c0 * 4, gr + bj * 128 + c0);
        }
        cp_commit();
    };

    issue(0, m0);
    for (int s = 0; s < 40; s++) {
        int b = s & 1;
        cp_wait0();
        __syncthreads();
        if (s < 39) issue(b ^ 1, m0 + (s + 1) * 32);
        float* SA = smem + b * (2 * TILEF);
        float* SB = diag ? SA : (SA + TILEF);
#pragma unroll
        for (int ks = 0; ks < 4; ks++) {
            int k0 = ks * 8;
            unsigned af[4][4], bf[4][2];
#pragma unroll
            for (int mf = 0; mf < 4; mf++) {
                int r0 = wy * 64 + mf * 16;
                af[mf][0] = f2tf(SA[(k0 + tg) * SSTR + r0 + g]);
                af[mf][1] = f2tf(SA[(k0 + tg) * SSTR + r0 + g + 8]);
                af[mf][2] = f2tf(SA[(k0 + tg + 4) * SSTR + r0 + g]);
                af[mf][3] = f2tf(SA[(k0 + tg + 4) * SSTR + r0 + g + 8]);
            }
#pragma unroll
            for (int nf = 0; nf < 4; nf++) {
                int c0 = wx * 32 + nf * 8;
                bf[nf][0] = f2tf(SB[(k0 + tg) * SSTR + c0 + g]);
                bf[nf][1] = f2tf(SB[(k0 + tg + 4) * SSTR + c0 + g]);
            }
#pragma unroll
            for (int mf = 0; mf < 4; mf++)
#pragma unroll
                for (int nf = 0; nf < 4; nf++)
                    mma_tf32(acc[mf][nf], af[mf], bf[nf]);
        }
        __syncthreads();
    }
    float* gp = g_Gp[blockIdx.y];
#pragma unroll
    for (int mf = 0; mf < 4; mf++) {
        int r0 = bi * 128 + wy * 64 + mf * 16 + g;
#pragma unroll
        for (int nf = 0; nf < 4; nf++) {
            int c0 = bj * 128 + wx * 32 + nf * 8 + 2 * tg;
            *(float2*)&gp[(size_t)r0 * R_ + c0]       = make_float2(acc[mf][nf][0], acc[mf][nf][1]);
            *(float2*)&gp[(size_t)(r0 + 8) * R_ + c0] = make_float2(acc[mf][nf][2], acc[mf][nf][3]);
        }
    }
}

// ---------------- sigma (lower only) ----------------
__global__ void sigma_kernel() {
    int gid = blockIdx.x * 256 + threadIdx.x;   // 4096 blocks
    int i = gid >> 10, j = gid & 1023;
    if (j > i) return;
    size_t lo = (size_t)i * R_ + j;
    float s = 0.f;
#pragma unroll
    for (int z = 0; z < KSPLIT; z++) s += g_Gp[z][lo];
    float corr = 0.f;
#pragma unroll
    for (int c = 0; c < C_; c++) corr += g_mu[c * R_ + i] * g_mu[c * R_ + j];
    float v = (s - (float)Q_ * corr) * (1.f / (float)M_);
    if (i == j) v += 1e-4f;
    g_S[lo] = v;
}

// ---------------- persistent one-kernel blocked Cholesky (B=64, 16 panels) ----------------
__device__ __forceinline__ void grid_bar(int id) {
    __syncthreads();
    if (threadIdx.x == 0) {
        __threadfence();                       // release + (sm_103a) L1D invalidate
        atomicAdd(&g_bars[id], 1);
        while (*(volatile int*)&g_bars[id] < CHB) { __nanosleep(32); }
        __threadfence();                       // acquire + L1D invalidate
    }
    __syncthreads();
}

__global__ __launch_bounds__(256) void chol_kernel() {
    __shared__ float L11[64][65];
    __shared__ float invd[64];
    __shared__ float As[64][65];
    __shared__ float Bs[64][65];
    int bid = blockIdx.x, tid = threadIdx.x;
    int barid = 0;

    for (int p = 0; p < 16; p++) {
        int o = p * 64, o2 = o + 64;
        // ---- phase 1: potf2 on diag block (block 0 only) ----
        if (bid == 0) {
            for (int idx = tid; idx < 4096; idx += 256) {
                int i = idx >> 6, j = idx & 63;
                L11[i][j] = (j <= i) ? g_S[(size_t)(o + i) * R_ + o + j] : 0.f;
            }
            __syncthreads();
            for (int k = 0; k < 64; k++) {
                if (tid == 0) L11[k][k] = sqrtf(L11[k][k]);
                __syncthreads();
                float d = L11[k][k];
                for (int i = k + 1 + tid; i < 64; i += 256) L11[i][k] /= d;
                __syncthreads();
                int n = 63 - k;
                for (int idx = tid; idx < n * n; idx += 256) {
                    int i = k + 1 + idx / n, j = k + 1 + idx % n;
                    if (j <= i) L11[i][j] -= L11[i][k] * L11[j][k];
                }
                __syncthreads();
            }
            for (int idx = tid; idx < 4096; idx += 256) {
                int i = idx >> 6, j = idx & 63;
                if (j <= i) g_S[(size_t)(o + i) * R_ + o + j] = L11[i][j];
            }
        }
        grid_bar(barid++);

        int nr = R_ - o2;
        // ---- phase 2: TRSM rows (all blocks) ----
        if (nr > 0) {
            for (int idx = tid; idx < 4096; idx += 256) {
                int i = idx >> 6, j = idx & 63;
                L11[i][j] = (j <= i) ? g_S[(size_t)(o + i) * R_ + o + j] : 0.f;
            }
            __syncthreads();
            if (tid < 64) invd[tid] = 1.f / L11[tid][tid];
            __syncthreads();
            int rr = bid * 256 + tid;
            if (rr < nr) {
                int r = o2 + rr;
                float row[64];
                float* gptr = g_S + (size_t)r * R_ + o;
#pragma unroll
                for (int j = 0; j < 64; j++) row[j] = gptr[j];
#pragma unroll
                for (int j = 0; j < 64; j++) {
                    float a = row[j];
#pragma unroll
                    for (int k = 0; k < j; k++) a -= row[k] * L11[j][k];
                    row[j] = a * invd[j];
                }
#pragma unroll
                for (int j = 0; j < 64; j++) gptr[j] = row[j];
            }
        }
        grid_bar(barid++);

        // ---- phase 3: trailing SYRK update (all blocks, tile-strided) ----
        if (nr > 0) {
            int nt = nr >> 6;
            int ntiles = nt * (nt + 1) / 2;
            for (int t = bid; t < ntiles; t += CHB) {
                __syncthreads();
                int bi = 0;
                while ((bi + 1) * (bi + 2) / 2 <= t) bi++;
                int bj = t - bi * (bi + 1) / 2;
                for (int idx = tid; idx < 4096; idx += 256) {
                    int i = idx >> 6, j = idx & 63;
                    As[i][j] = g_S[(size_t)(o2 + bi * 64 + i) * R_ + o + j];
                    Bs[i][j] = g_S[(size_t)(o2 + bj * 64 + i) * R_ + o + j];
                }
                __syncthreads();
                int tx = tid & 15, ty = tid >> 4;
                float acc[4][4];
#pragma unroll
                for (int r = 0; r < 4; r++)
#pragma unroll
                    for (int c = 0; c < 4; c++) acc[r][c] = 0.f;
#pragma unroll 8
                for (int k = 0; k < 64; k++) {
                    float a[4], b[4];
#pragma unroll
                    for (int r = 0; r < 4; r++) a[r] = As[ty * 4 + r][k];
#pragma unroll
                    for (int c = 0; c < 4; c++) b[c] = Bs[tx * 4 + c][k];
#pragma unroll
                    for (int r = 0; r < 4; r++)
#pragma unroll
                        for (int c = 0; c < 4; c++) acc[r][c] = fmaf(a[r], b[c], acc[r][c]);
                }
#pragma unroll
                for (int r = 0; r < 4; r++)
#pragma unroll
                    for (int c = 0; c < 4; c++)
                        g_S[(size_t)(o2 + bi * 64 + ty * 4 + r) * R_ + o2 + bj * 64 + tx * 4 + c] -= acc[r][c];
            }
        }
        grid_bar(barid++);
    }
}

// ---------------- ||eps||^2 per row + per-class argmax (first-index tie-break) ----------------
__global__ void sq_kernel(const float* __restrict__ eps) {
    int row = blockIdx.x * 8 + (threadIdx.x >> 5);   // 12500 blocks x 8 warps
    int lane = threadIdx.x & 31;
    const float4* p = (const float4*)(eps + (size_t)row * R_);
    float ss = 0.f;
#pragma unroll
    for (int it = 0; it < 8; it++) {
        float4 v = p[lane + it * 32];
        ss = fmaf(v.x, v.x, fmaf(v.y, v.y, fmaf(v.z, v.z, fmaf(v.w, v.w, ss))));
    }
#pragma unroll
    for (int o = 16; o; o >>= 1) ss += __shfl_xor_sync(0xffffffffu, ss, o);
    if (lane == 0) {
        int c = row / S_;
        unsigned s = (unsigned)(row - c * S_);
        unsigned long long key = ((unsigned long long)__float_as_uint(ss) << 32)
                               | (unsigned long long)(0xFFFFFFFFu - s);
        atomicMax(&g_amax[c], key);
    }
}

__global__ void gather_kernel(const float* __restrict__ eps) {
    int c = blockIdx.x;
    unsigned s = 0xFFFFFFFFu - (unsigned)(g_amax[c] & 0xFFFFFFFFull);
    const float4* src = (const float4*)(eps + ((size_t)c * S_ + s) * R_);
    ((float4*)(g_eps_sel + c * R_))[threadIdx.x] = src[threadIdx.x];
}

// ---------------- vos = mu + L @ eps_sel ----------------
__global__ void vos_kernel() {                  // grid 16 blocks x 256 thr, 64 rows/block
    __shared__ float e[C_][R_];                 // 40 KB
    int tid = threadIdx.x;
    for (int i = tid; i < C_ * R_; i += 256) ((float*)e)[i] = g_eps_sel[i];
    __syncthreads();
    int w = tid >> 5, lane = tid & 31;
    for (int rr = 0; rr < 8; rr++) {
        int i = blockIdx.x * 64 + rr * 8 + w;
        const float* Lr = g_S + (size_t)i * R_;
        float p[C_];
#pragma unroll
        for (int c = 0; c < C_; c++) p[c] = 0.f;
        for (int j = lane; j <= i; j += 32) {
            float Lv = Lr[j];
#pragma unroll
            for (int c = 0; c < C_; c++) p[c] = fmaf(Lv, e[c][j], p[c]);
        }
#pragma unroll
        for (int c = 0; c < C_; c++) {
            float v = p[c];
#pragma unroll
            for (int o = 16; o; o >>= 1) v += __shfl_xor_sync(0xffffffffu, v, o);
            if (lane == 0) g_vos[c * R_ + i] = g_mu[c * R_ + i] + v;
        }
    }
}

// ---------------- scores + focal (cls path) ----------------
__global__ void scores_cls_kernel(const float* __restrict__ X, const float* __restrict__ W,
                                  const float* __restrict__ b, const int* __restrict__ labels) {
    __shared__ float red[C_][8];
    __shared__ float srow[C_];
    int row = blockIdx.x, tid = threadIdx.x;    // 512 blocks x 256
    float acc[C_];
#pragma unroll
    for (int c = 0; c < C_; c++) acc[c] = 0.f;
    const float* x = X + (size_t)row * R_;
    for (int r = tid; r < R_; r += 256) {
        float xv = x[r];
#pragma unroll
        for (int c = 0; c < C_; c++) acc[c] = fmaf(xv, W[c * R_ + r], acc[c]);
    }
#pragma unroll
    for (int c = 0; c < C_; c++) {
        float v = acc[c];
#pragma unroll
        for (int o = 16; o; o >>= 1) v += __shfl_xor_sync(0xffffffffu, v, o);
        acc[c] = v;
    }
    int w = tid >> 5, lane = tid & 31;
    if (lane == 0)
#pragma unroll
        for (int c = 0; c < C_; c++) red[c][w] = acc[c];
    __syncthreads();
    if (tid < C_) {
        float s = red[tid][0];
#pragma unroll
        for (int ww = 1; ww < 8; ww++) s += red[tid][ww];
        s += b[tid];
        g_scores[row * C_ + tid] = s;
        srow[tid] = s;
    }
    __syncthreads();
    if (tid == 0) {
        int lab = labels[row];
        float fs = 0.f;
#pragma unroll
        for (int c = 0; c < C_; c++) {
            float xv = srow[c];
            float tt = (c == lab) ? 1.f : 0.f;
            float ce = fmaxf(xv, 0.f) - xv * tt + log1pf(expf(-fabsf(xv)));
            float pp = 1.f / (1.f + expf(-xv));
            float pt = pp * tt + (1.f - pp) * (1.f - tt);
            float at = 0.25f * tt + 0.75f * (1.f - tt);
            float om = 1.f - pt;
            fs += at * ce * om * om;
        }
        g_focal[row] = fs;
    }
}

// ---------------- scores_vos = vos @ W^T + b ----------------
__global__ void scores_vos_kernel(const float* __restrict__ W, const float* __restrict__ b) {
    __shared__ float red[C_][8];
    int row = blockIdx.x, tid = threadIdx.x;    // 10 blocks x 256
    float acc[C_];
#pragma unroll
    for (int c = 0; c < C_; c++) acc[c] = 0.f;
    const float* x = g_vos + (size_t)row * R_;
    for (int r = tid; r < R_; r += 256) {
        float xv = x[r];
#pragma unroll
        for (int c = 0; c < C_; c++) acc[c] = fmaf(xv, W[c * R_ + r], acc[c]);
    }
#pragma unroll
    for (int c = 0; c < C_; c++) {
        float v = acc[c];
#pragma unroll
        for (int o = 16; o; o >>= 1) v += __shfl_xor_sync(0xffffffffu, v, o);
        acc[c] = v;
    }
    int w = tid >> 5, lane = tid & 31;
    if (lane == 0)
#pragma unroll
        for (int c = 0; c < C_; c++) red[c][w] = acc[c];
    __syncthreads();
    if (tid < C_) {
        float s = red[tid][0];
#pragma unroll
        for (int ww = 1; ww < 8; ww++) s += red[tid][ww];
        g_scores_vos[row * C_ + tid] = s + b[tid];
    }
}

// ---------------- energy -> MLP -> BCE, plus focal reduction ----------------
__global__ void final_kernel(const float* __restrict__ w_e, const float* __restrict__ W1,
                             const float* __restrict__ b1, const float* __restrict__ W2,
                             const float* __restrict__ b2, float* __restrict__ out) {
    __shared__ float we[C_];
    __shared__ float bce[544];
    __shared__ float foc[N_];
    int tid = threadIdx.x;                      // 544 threads
    if (tid < C_) we[tid] = fmaxf(w_e[tid], 0.f);
    for (int i = tid; i < N_; i += 544) foc[i] = g_focal[i];
    __syncthreads();
    float v = 0.f;
    if (tid < N_ + C_) {
        const float* row = (tid < N_) ? (g_scores + tid * C_) : (g_scores_vos + (tid - N_) * C_);
        float m = row[0];
#pragma unroll
        for (int c = 1; c < C_; c++) m = fmaxf(m, row[c]);
        float ssum = 0.f;
#pragma unroll
        for (int c = 0; c < C_; c++) ssum += expf(row[c] - m) * we[c];
        float e = m + logf(ssum);
        float lg = 0.f;
        for (int j = 0; j < 512; j++) lg = fmaf(fmaxf(fmaf(e, W1[j], b1[j]), 0.f), W2[j], lg);
        lg += b2[0];
        float y = (tid < N_) ? 1.f : 0.f;
        v = fmaxf(lg, 0.f) - lg * y + log1pf(expf(-fabsf(lg)));
    }
    bce[tid] = v;
    __syncthreads();
    if (tid == 0) {
        float bs = 0.f;
        for (int i = 0; i < N_ + C_; i++) bs += bce[i];
        float fsum = 0.f;
        for (int i = 0; i < N_; i++) fsum += foc[i];
        out[0] = fsum / (float)N_;
        out[1] = 0.1f * bs / (float)(N_ + C_);
    }
}

// ---------------- launch ----------------
extern "C" void kernel_launch(void* const* d_in, const int* in_sizes, int n_in,
                              void* d_out, int out_size) {
    const float* box     = (const float*)d_in[0];
    const int*   labels  = (const int*)d_in[1];
    const float* id_data = (const float*)d_in[2];
    const float* W_pred  = (const float*)d_in[4];
    const float* b_pred  = (const float*)d_in[5];
    const float* w_e     = (const float*)d_in[6];
    const float* dW1     = (const float*)d_in[7];
    const float* db1     = (const float*)d_in[8];
    const float* dW2     = (const float*)d_in[9];
    const float* db2     = (const float*)d_in[10];
    const float* eps     = (const float*)d_in[11];
    float* out = (float*)d_out;
    (void)in_sizes; (void)n_in; (void)out_size;

    cudaFuncSetAttribute(syrk_kernel, cudaFuncAttributeMaxDynamicSharedMemorySize, SYRK_SMEM);

    order_kernel<<<1, 512>>>(labels);                       // 1
    matD_kernel<<<MP, 256>>>(id_data, box);                 // 2
    mu_part_kernel<<<NMCH, 256>>>();                        // 3
    syrk_kernel<<<dim3(36, KSPLIT), 256, SYRK_SMEM>>>();    // 4  <- profiled
    mu_reduce_kernel<<<(C_ * R_) / 256, 256>>>();           // 5
    sq_kernel<<<(C_ * S_) / 8, 256>>>(eps);                 // 6
    sigma_kernel<<<(R_ * R_) / 256, 256>>>();               // 7
    chol_kernel<<<CHB, 256>>>();                            // 8
    gather_kernel<<<C_, 256>>>(eps);                        // 9
    vos_kernel<<<16, 256>>>();                              // 10
    scores_cls_kernel<<<N_, 256>>>(box, W_pred, b_pred, labels); // 11
    scores_vos_kernel<<<C_, 256>>>(W_pred, b_pred);         // 12
    final_kernel<<<1, 544>>>(w_e, dW1, db1, dW2, db2, out); // 13
}

// round 14
// speedup vs baseline: 1.6853x; 1.1529x over previous
#include <cuda_runtime.h>
#include <math.h>

#define C_ 10
#define Q_ 1000
#define R_ 1024
#define N_ 512
#define S_ 10000
#define M_ 10000          // C_*Q_
#define MP 10240          // padded rows (zero-filled) -> 8 chunks x 1280, 40 steps of 32
#define KSPLIT 8
#define CHUNKP 1280       // MP/KSPLIT
#define MCH 40            // mu chunk rows
#define NMCH 250          // M_/MCH
#define SSTR 136          // SMEM row stride (floats): conflict-free frag loads
#define TILEF (32*SSTR)   // floats per tile buffer
#define SYRK_SMEM (4*TILEF*4)   // 2 bufs x (A+B) = 69632 bytes
#define CHB 120           // persistent-Cholesky blocks (1 wave on 148 SMs)

// ---------------- static device scratch (no allocations allowed) ----------------
static __device__ float g_D[MP * R_];                  // updated queues (padded), 41.9 MB
static __device__ float g_Gp[KSPLIT][R_ * R_];         // SYRK partials (lower), 33.5 MB
static __device__ float g_S[R_ * R_];                  // sigma (lower) -> L in place
static __device__ float g_mup[NMCH * R_];              // mu partials
static __device__ float g_mu[C_ * R_];
static __device__ float g_scores[N_ * C_];
static __device__ float g_scores_vos[C_ * C_];
static __device__ float g_eps_sel[C_ * R_];
static __device__ float g_vos[C_ * R_];
static __device__ float g_focal[N_];
static __device__ int   g_order[C_ * N_];
static __device__ int   g_cnt[C_];
static __device__ unsigned long long g_amax[C_];
static __device__ int   g_bars[64];

// ---------------- per-class sample ordering + replay-state reset ----------------
__global__ void order_kernel(const int* __restrict__ labels) {
    __shared__ int labs[N_];
    int tid = threadIdx.x;                   // 512 threads
    labs[tid] = labels[tid];
    if (tid < C_) { g_cnt[tid] = 0; g_amax[tid] = 0ull; }
    if (tid < 64) g_bars[tid] = 0;
    __syncthreads();
    int lab = labs[tid];
    int pos = 0;
    for (int j = 0; j < tid; j++) pos += (labs[j] == lab) ? 1 : 0;
    g_order[lab * N_ + pos] = tid;
    atomicAdd(&g_cnt[lab], 1);
}

// ---------------- materialize updated queue data D (padded with zeros) ----------------
__global__ void matD_kernel(const float* __restrict__ id_data, const float* __restrict__ box) {
    int row = blockIdx.x;                    // 0..MP-1
    if (row >= M_) {
        ((float4*)(g_D + (size_t)row * R_))[threadIdx.x] = make_float4(0.f, 0.f, 0.f, 0.f);
        return;
    }
    int c = row / Q_, q = row - c * Q_;
    int k = g_cnt[c];
    const float* src;
    if (q < Q_ - k) src = id_data + (size_t)(c * Q_ + q + k) * R_;
    else            src = box + (size_t)g_order[c * N_ + q - (Q_ - k)] * R_;
    ((float4*)(g_D + (size_t)row * R_))[threadIdx.x] = ((const float4*)src)[threadIdx.x];
}

// ---------------- per-class mean: coalesced chunk partials + reduce ----------------
__global__ void mu_part_kernel() {                     // grid 250, 256 thr
    int z = blockIdx.x;
    const float4* base = (const float4*)(g_D + (size_t)z * MCH * R_);
    float4 s = make_float4(0.f, 0.f, 0.f, 0.f);
    for (int q = 0; q < MCH; q++) {
        float4 v = base[q * (R_ / 4) + threadIdx.x];
        s.x += v.x; s.y += v.y; s.z += v.z; s.w += v.w;
    }
    ((float4*)g_mup)[z * (R_ / 4) + threadIdx.x] = s;
}
__global__ void mu_reduce_kernel() {                   // grid 40, 256 thr
    int gid = blockIdx.x * 256 + threadIdx.x;          // 10240 = C_*R_
    int c = gid >> 10, r = gid & 1023;
    float s = 0.f;
#pragma unroll
    for (int z = 0; z < NMCH / C_; z++) s += g_mup[(c * (NMCH / C_) + z) * R_ + r];
    g_mu[gid] = s * (1.f / (float)Q_);
}

// ---------------- tf32 tensor-core SYRK with cp.async double buffering ----------------
__device__ __forceinline__ unsigned f2tf(float x) {
    unsigned r; asm("cvt.rna.tf32.f32 %0, %1;" : "=r"(r) : "f"(x)); return r;
}
__device__ __forceinline__ void mma_tf32(float* d, const unsigned* a, const unsigned* b) {
    asm volatile(
        "mma.sync.aligned.m16n8k8.row.col.f32.tf32.tf32.f32 "
        "{%0,%1,%2,%3}, {%4,%5,%6,%7}, {%8,%9}, {%0,%1,%2,%3};\n"
        : "+f"(d[0]), "+f"(d[1]), "+f"(d[2]), "+f"(d[3])
        : "r"(a[0]), "r"(a[1]), "r"(a[2]), "r"(a[3]), "r"(b[0]), "r"(b[1]));
}
__device__ __forceinline__ void cpasync16(unsigned saddr, const void* g) {
    asm volatile("cp.async.ca.shared.global [%0], [%1], 16;\n" :: "r"(saddr), "l"(g));
}
__device__ __forceinline__ void cp_commit() { asm volatile("cp.async.commit_group;\n"); }
__device__ __forceinline__ void cp_wait0()  { asm volatile("cp.async.wait_group 0;\n"); }

__global__ __launch_bounds__(256, 2) void syrk_kernel() {
    extern __shared__ float smem[];
    int t = blockIdx.x;
    int bi = 0;
    while ((bi + 1) * (bi + 2) / 2 <= t) bi++;
    int bj = t - bi * (bi + 1) / 2;
    bool diag = (bi == bj);

    int tid = threadIdx.x;
    int wid = tid >> 5, lane = tid & 31;
    int wy = wid & 1, wx = wid >> 1;         // warp tile: rows wy*64, cols wx*32
    int g = lane >> 2, tg = lane & 3;
    int lr = tid >> 3;                       // load row 0..31
    int lc = tid & 7;                        // load col-quarter base

    int m0 = blockIdx.y * CHUNKP;

    float acc[4][4][4];
#pragma unroll
    for (int mf = 0; mf < 4; mf++)
#pragma unroll
        for (int nf = 0; nf < 4; nf++)
#pragma unroll
            for (int q = 0; q < 4; q++) acc[mf][nf][q] = 0.f;

    auto issue = [&](int b, int mb) {
        float* SA = smem + b * (2 * TILEF);
        float* SB = SA + TILEF;
        const float* gr = g_D + (size_t)(mb + lr) * R_;
        unsigned sA = (unsigned)__cvta_generic_to_shared(SA + lr * SSTR);
        unsigned sB = (unsigned)__cvta_generic_to_shared(SB + lr * SSTR);
#pragma unroll
        for (int i = 0; i < 4; i++) {
            int c0 = (lc + 8 * i) * 4;       // float offset within 128-col panel
            cpasync16(sA + c0 * 4, gr + bi * 128 + c0);
            if (!diag) cpasync16(sB + c0 * 4, gr + bj * 128 + c0);
        }
        cp_commit();
    };

    issue(0, m0);
    for (int s = 0; s < 40; s++) {
        int b = s & 1;
        cp_wait0();
        __syncthreads();
        if (s < 39) issue(b ^ 1, m0 + (s + 1) * 32);
        float* SA = smem + b * (2 * TILEF);
        float* SB = diag ? SA : (SA + TILEF);
#pragma unroll
        for (int ks = 0; ks < 4; ks++) {
            int k0 = ks * 8;
            unsigned af[4][4], bf[4][2];
#pragma unroll
            for (int mf = 0; mf < 4; mf++) {
                int r0 = wy * 64 + mf * 16;
                af[mf][0] = f2tf(SA[(k0 + tg) * SSTR + r0 + g]);
                af[mf][1] = f2tf(SA[(k0 + tg) * SSTR + r0 + g + 8]);
                af[mf][2] = f2tf(SA[(k0 + tg + 4) * SSTR + r0 + g]);
                af[mf][3] = f2tf(SA[(k0 + tg + 4) * SSTR + r0 + g + 8]);
            }
#pragma unroll
            for (int nf = 0; nf < 4; nf++) {
                int c0 = wx * 32 + nf * 8;
                bf[nf][0] = f2tf(SB[(k0 + tg) * SSTR + c0 + g]);
                bf[nf][1] = f2tf(SB[(k0 + tg + 4) * SSTR + c0 + g]);
            }
#pragma unroll
            for (int mf = 0; mf < 4; mf++)
#pragma unroll
                for (int nf = 0; nf < 4; nf++)
                    mma_tf32(acc[mf][nf], af[mf], bf[nf]);
        }
        __syncthreads();
    }
    float* gp = g_Gp[blockIdx.y];
#pragma unroll
    for (int mf = 0; mf < 4; mf++) {
        int r0 = bi * 128 + wy * 64 + mf * 16 + g;
#pragma unroll
        for (int nf = 0; nf < 4; nf++) {
            int c0 = bj * 128 + wx * 32 + nf * 8 + 2 * tg;
            *(float2*)&gp[(size_t)r0 * R_ + c0]       = make_float2(acc[mf][nf][0], acc[mf][nf][1]);
            *(float2*)&gp[(size_t)(r0 + 8) * R_ + c0] = make_float2(acc[mf][nf][2], acc[mf][nf][3]);
        }
    }
}

// ---------------- sigma (lower only) ----------------
__global__ void sigma_kernel() {
    int gid = blockIdx.x * 256 + threadIdx.x;   // 4096 blocks
    int i = gid >> 10, j = gid & 1023;
    if (j > i) return;
    size_t lo = (size_t)i * R_ + j;
    float s = 0.f;
#pragma unroll
    for (int z = 0; z < KSPLIT; z++) s += g_Gp[z][lo];
    float corr = 0.f;
#pragma unroll
    for (int c = 0; c < C_; c++) corr += g_mu[c * R_ + i] * g_mu[c * R_ + j];
    float v = (s - (float)Q_ * corr) * (1.f / (float)M_);
    if (i == j) v += 1e-4f;
    g_S[lo] = v;
}

// ---------------- persistent one-kernel blocked Cholesky (B=64, 16 panels) ----------------
// potf2 is computed REDUNDANTLY by every block (shift/mask indexing only, 2 syncs/k),
// so TRSM uses the locally-held L11 with no grid barrier after potf2.
// Grid barriers: after TRSM and after trailing update -> 32 total.
__device__ __forceinline__ void grid_bar(int id) {
    __syncthreads();
    if (threadIdx.x == 0) {
        __threadfence();
        atomicAdd(&g_bars[id], 1);
        while (*(volatile int*)&g_bars[id] < CHB) { __nanosleep(32); }
        __threadfence();
    }
    __syncthreads();
}

__global__ __launch_bounds__(256) void chol_kernel() {
    __shared__ float P[64][65];     // diag panel -> L11 (redundant per block)
    __shared__ float invd[64];
    __shared__ float As[64][65];
    __shared__ float Bs[64][65];
    int bid = blockIdx.x, tid = threadIdx.x;
    int barid = 0;

    for (int p = 0; p < 16; p++) {
        int o = p * 64, o2 = o + 64;
        int nr = R_ - o2;

        // ---- load diag panel (all blocks) ----
        for (int idx = tid; idx < 4096; idx += 256) {
            int i = idx >> 6, j = idx & 63;
            P[i][j] = (j <= i) ? g_S[(size_t)(o + i) * R_ + o + j] : 0.f;
        }
        __syncthreads();

        // ---- in-shared potf2, 2 syncs per k, no div/mod ----
        for (int k = 0; k < 64; k++) {
            float d = P[k][k];                 // all threads read BEFORE any write
            float sd = sqrtf(d);
            int i = k + 1 + tid;
            if (i < 64) P[i][k] /= sd;         // divide column k (disjoint writes)
            __syncthreads();
            if (tid == 0) P[k][k] = sd;        // deferred store (disjoint from update)
            int n = 63 - k;
            for (int idx = tid; idx < n * 64; idx += 256) {
                int i2 = k + 1 + (idx >> 6);
                int j2 = idx & 63;
                if (j2 > k && j2 <= i2) P[i2][j2] -= P[i2][k] * P[j2][k];
            }
            __syncthreads();
        }
        if (tid < 64) invd[tid] = 1.f / P[tid][tid];
        __syncthreads();

        // ---- block 0 writes L11 back to global (no one reads it before kernel end) ----
        if (bid == 0) {
            for (int idx = tid; idx < 4096; idx += 256) {
                int i = idx >> 6, j = idx & 63;
                if (j <= i) g_S[(size_t)(o + i) * R_ + o + j] = P[i][j];
            }
        }

        // ---- TRSM rows (all blocks) using local P ----
        if (nr > 0) {
            int rr = bid * 256 + tid;
            if (rr < nr) {
                int r = o2 + rr;
                float row[64];
                float* gptr = g_S + (size_t)r * R_ + o;
#pragma unroll
                for (int j = 0; j < 64; j++) row[j] = gptr[j];
#pragma unroll
                for (int j = 0; j < 64; j++) {
                    float a = row[j];
#pragma unroll
                    for (int k = 0; k < j; k++) a -= row[k] * P[j][k];
                    row[j] = a * invd[j];
                }
#pragma unroll
                for (int j = 0; j < 64; j++) gptr[j] = row[j];
            }
        }
        grid_bar(barid++);

        // ---- trailing SYRK update (all blocks, tile-strided) ----
        if (nr > 0) {
            int nt = nr >> 6;
            int ntiles = nt * (nt + 1) / 2;
            for (int t = bid; t < ntiles; t += CHB) {
                __syncthreads();
                int bi = 0;
                while ((bi + 1) * (bi + 2) / 2 <= t) bi++;
                int bj = t - bi * (bi + 1) / 2;
                for (int idx = tid; idx < 4096; idx += 256) {
                    int i = idx >> 6, j = idx & 63;
                    As[i][j] = g_S[(size_t)(o2 + bi * 64 + i) * R_ + o + j];
                    Bs[i][j] = g_S[(size_t)(o2 + bj * 64 + i) * R_ + o + j];
                }
                __syncthreads();
                int tx = tid & 15, ty = tid >> 4;
                float acc[4][4];
#pragma unroll
                for (int r = 0; r < 4; r++)
#pragma unroll
                    for (int c = 0; c < 4; c++) acc[r][c] = 0.f;
#pragma unroll 8
                for (int k = 0; k < 64; k++) {
                    float a[4], b[4];
#pragma unroll
                    for (int r = 0; r < 4; r++) a[r] = As[ty * 4 + r][k];
#pragma unroll
                    for (int c = 0; c < 4; c++) b[c] = Bs[tx * 4 + c][k];
#pragma unroll
                    for (int r = 0; r < 4; r++)
#pragma unroll
                        for (int c = 0; c < 4; c++) acc[r][c] = fmaf(a[r], b[c], acc[r][c]);
                }
#pragma unroll
                for (int r = 0; r < 4; r++)
#pragma unroll
                    for (int c = 0; c < 4; c++)
                        g_S[(size_t)(o2 + bi * 64 + ty * 4 + r) * R_ + o2 + bj * 64 + tx * 4 + c] -= acc[r][c];
            }
        }
        grid_bar(barid++);
    }
}

// ---------------- ||eps||^2 per row + per-class argmax (first-index tie-break) ----------------
__global__ void sq_kernel(const float* __restrict__ eps) {
    int row = blockIdx.x * 8 + (threadIdx.x >> 5);   // 12500 blocks x 8 warps
    int lane = threadIdx.x & 31;
    const float4* p = (const float4*)(eps + (size_t)row * R_);
    float ss = 0.f;
#pragma unroll
    for (int it = 0; it < 8; it++) {
        float4 v = p[lane + it * 32];
        ss = fmaf(v.x, v.x, fmaf(v.y, v.y, fmaf(v.z, v.z, fmaf(v.w, v.w, ss))));
    }
#pragma unroll
    for (int o = 16; o; o >>= 1) ss += __shfl_xor_sync(0xffffffffu, ss, o);
    if (lane == 0) {
        int c = row / S_;
        unsigned s = (unsigned)(row - c * S_);
        unsigned long long key = ((unsigned long long)__float_as_uint(ss) << 32)
                               | (unsigned long long)(0xFFFFFFFFu - s);
        atomicMax(&g_amax[c], key);
    }
}

__global__ void gather_kernel(const float* __restrict__ eps) {
    int c = blockIdx.x;
    unsigned s = 0xFFFFFFFFu - (unsigned)(g_amax[c] & 0xFFFFFFFFull);
    const float4* src = (const float4*)(eps + ((size_t)c * S_ + s) * R_);
    ((float4*)(g_eps_sel + c * R_))[threadIdx.x] = src[threadIdx.x];
}

// ---------------- vos = mu + L @ eps_sel ----------------
__global__ void vos_kernel() {                  // grid 16 blocks x 256 thr, 64 rows/block
    __shared__ float e[C_][R_];                 // 40 KB
    int tid = threadIdx.x;
    for (int i = tid; i < C_ * R_; i += 256) ((float*)e)[i] = g_eps_sel[i];
    __syncthreads();
    int w = tid >> 5, lane = tid & 31;
    for (int rr = 0; rr < 8; rr++) {
        int i = blockIdx.x * 64 + rr * 8 + w;
        const float* Lr = g_S + (size_t)i * R_;
        float p[C_];
#pragma unroll
        for (int c = 0; c < C_; c++) p[c] = 0.f;
        for (int j = lane; j <= i; j += 32) {
            float Lv = Lr[j];
#pragma unroll
            for (int c = 0; c < C_; c++) p[c] = fmaf(Lv, e[c][j], p[c]);
        }
#pragma unroll
        for (int c = 0; c < C_; c++) {
            float v = p[c];
#pragma unroll
            for (int o = 16; o; o >>= 1) v += __shfl_xor_sync(0xffffffffu, v, o);
            if (lane == 0) g_vos[c * R_ + i] = g_mu[c * R_ + i] + v;
        }
    }
}

// ---------------- scores + focal (cls path) ----------------
__global__ void scores_cls_kernel(const float* __restrict__ X, const float* __restrict__ W,
                                  const float* __restrict__ b, const int* __restrict__ labels) {
    __shared__ float red[C_][8];
    __shared__ float srow[C_];
    int row = blockIdx.x, tid = threadIdx.x;    // 512 blocks x 256
    float acc[C_];
#pragma unroll
    for (int c = 0; c < C_; c++) acc[c] = 0.f;
    const float* x = X + (size_t)row * R_;
    for (int r = tid; r < R_; r += 256) {
        float xv = x[r];
#pragma unroll
        for (int c = 0; c < C_; c++) acc[c] = fmaf(xv, W[c * R_ + r], acc[c]);
    }
#pragma unroll
    for (int c = 0; c < C_; c++) {
        float v = acc[c];
#pragma unroll
        for (int o = 16; o; o >>= 1) v += __shfl_xor_sync(0xffffffffu, v, o);
        acc[c] = v;
    }
    int w = tid >> 5, lane = tid & 31;
    if (lane == 0)
#pragma unroll
        for (int c = 0; c < C_; c++) red[c][w] = acc[c];
    __syncthreads();
    if (tid < C_) {
        float s = red[tid][0];
#pragma unroll
        for (int ww = 1; ww < 8; ww++) s += red[tid][ww];
        s += b[tid];
        g_scores[row * C_ + tid] = s;
        srow[tid] = s;
    }
    __syncthreads();
    if (tid == 0) {
        int lab = labels[row];
        float fs = 0.f;
#pragma unroll
        for (int c = 0; c < C_; c++) {
            float xv = srow[c];
            float tt = (c == lab) ? 1.f : 0.f;
            float ce = fmaxf(xv, 0.f) - xv * tt + log1pf(expf(-fabsf(xv)));
            float pp = 1.f / (1.f + expf(-xv));
            float pt = pp * tt + (1.f - pp) * (1.f - tt);
            float at = 0.25f * tt + 0.75f * (1.f - tt);
            float om = 1.f - pt;
            fs += at * ce * om * om;
        }
        g_focal[row] = fs;
    }
}

// ---------------- scores_vos = vos @ W^T + b ----------------
__global__ void scores_vos_kernel(const float* __restrict__ W, const float* __restrict__ b) {
    __shared__ float red[C_][8];
    int row = blockIdx.x, tid = threadIdx.x;    // 10 blocks x 256
    float acc[C_];
#pragma unroll
    for (int c = 0; c < C_; c++) acc[c] = 0.f;
    const float* x = g_vos + (size_t)row * R_;
    for (int r = tid; r < R_; r += 256) {
        float xv = x[r];
#pragma unroll
        for (int c = 0; c < C_; c++) acc[c] = fmaf(xv, W[c * R_ + r], acc[c]);
    }
#pragma unroll
    for (int c = 0; c < C_; c++) {
        float v = acc[c];
#pragma unroll
        for (int o = 16; o; o >>= 1) v += __shfl_xor_sync(0xffffffffu, v, o);
        acc[c] = v;
    }
    int w = tid >> 5, lane = tid & 31;
    if (lane == 0)
#pragma unroll
        for (int c = 0; c < C_; c++) red[c][w] = acc[c];
    __syncthreads();
    if (tid < C_) {
        float s = red[tid][0];
#pragma unroll
        for (int ww = 1; ww < 8; ww++) s += red[tid][ww];
        g_scores_vos[row * C_ + tid] = s + b[tid];
    }
}

// ---------------- energy -> MLP -> BCE, plus focal reduction ----------------
__global__ void final_kernel(const float* __restrict__ w_e, const float* __restrict__ W1,
                             const float* __restrict__ b1, const float* __restrict__ W2,
                             const float* __restrict__ b2, float* __restrict__ out) {
    __shared__ float we[C_];
    __shared__ float bce[544];
    __shared__ float foc[N_];
    int tid = threadIdx.x;                      // 544 threads
    if (tid < C_) we[tid] = fmaxf(w_e[tid], 0.f);
    for (int i = tid; i < N_; i += 544) foc[i] = g_focal[i];
    __syncthreads();
    float v = 0.f;
    if (tid < N_ + C_) {
        const float* row = (tid < N_) ? (g_scores + tid * C_) : (g_scores_vos + (tid - N_) * C_);
        float m = row[0];
#pragma unroll
        for (int c = 1; c < C_; c++) m = fmaxf(m, row[c]);
        float ssum = 0.f;
#pragma unroll
        for (int c = 0; c < C_; c++) ssum += expf(row[c] - m) * we[c];
        float e = m + logf(ssum);
        float lg = 0.f;
        for (int j = 0; j < 512; j++) lg = fmaf(fmaxf(fmaf(e, W1[j], b1[j]), 0.f), W2[j], lg);
        lg += b2[0];
        float y = (tid < N_) ? 1.f : 0.f;
        v = fmaxf(lg, 0.f) - lg * y + log1pf(expf(-fabsf(lg)));
    }
    bce[tid] = v;
    __syncthreads();
    if (tid == 0) {
        float bs = 0.f;
        for (int i = 0; i < N_ + C_; i++) bs += bce[i];
        float fsum = 0.f;
        for (int i = 0; i < N_; i++) fsum += foc[i];
        out[0] = fsum / (float)N_;
        out[1] = 0.1f * bs / (float)(N_ + C_);
    }
}

// ---------------- launch ----------------
extern "C" void kernel_launch(void* const* d_in, const int* in_sizes, int n_in,
                              void* d_out, int out_size) {
    const float* box     = (const float*)d_in[0];
    const int*   labels  = (const int*)d_in[1];
    const float* id_data = (const float*)d_in[2];
    const float* W_pred  = (const float*)d_in[4];
    const float* b_pred  = (const float*)d_in[5];
    const float* w_e     = (const float*)d_in[6];
    const float* dW1     = (const float*)d_in[7];
    const float* db1     = (const float*)d_in[8];
    const float* dW2     = (const float*)d_in[9];
    const float* db2     = (const float*)d_in[10];
    const float* eps     = (const float*)d_in[11];
    float* out = (float*)d_out;
    (void)in_sizes; (void)n_in; (void)out_size;

    cudaFuncSetAttribute(syrk_kernel, cudaFuncAttributeMaxDynamicSharedMemorySize, SYRK_SMEM);

    order_kernel<<<1, 512>>>(labels);                       // 1
    matD_kernel<<<MP, 256>>>(id_data, box);                 // 2
    mu_part_kernel<<<NMCH, 256>>>();                        // 3
    sq_kernel<<<(C_ * S_) / 8, 256>>>(eps);                 // 4  <- profiled
    syrk_kernel<<<dim3(36, KSPLIT), 256, SYRK_SMEM>>>();    // 5
    mu_reduce_kernel<<<(C_ * R_) / 256, 256>>>();           // 6
    sigma_kernel<<<(R_ * R_) / 256, 256>>>();               // 7
    chol_kernel<<<CHB, 256>>>();                            // 8
    gather_kernel<<<C_, 256>>>(eps);                        // 9
    vos_kernel<<<16, 256>>>();                              // 10
    scores_cls_kernel<<<N_, 256>>>(box, W_pred, b_pred, labels); // 11
    scores_vos_kernel<<<C_, 256>>>(W_pred, b_pred);         // 12
    final_kernel<<<1, 544>>>(w_e, dW1, db1, dW2, db2, out); // 13
}

// round 15
// speedup vs baseline: 1.7257x; 1.0240x over previous
#include <cuda_runtime.h>
#include <math.h>

#define C_ 10
#define Q_ 1000
#define R_ 1024
#define N_ 512
#define S_ 10000
#define M_ 10000          // C_*Q_
#define MP 10240          // padded rows (zero-filled)
#define KSPLIT 8
#define CHUNKP 1280       // MP/KSPLIT
#define MCH 40            // mu chunk rows
#define NMCH 250          // M_/MCH
#define SSTR 136          // SYRK SMEM row stride (floats)
#define TILEF (32*SSTR)
#define SYRK_SMEM (4*TILEF*4)   // 69632 bytes
#define CHB 120           // persistent-Cholesky blocks

// ---------------- static device scratch ----------------
static __device__ float g_D[MP * R_];
static __device__ float g_Gp[KSPLIT][R_ * R_];
static __device__ float g_S[R_ * R_];
static __device__ float g_mup[NMCH * R_];
static __device__ float g_mu[C_ * R_];
static __device__ float g_scores[N_ * C_];
static __device__ float g_scores_vos[C_ * C_];
static __device__ float g_eps_sel[C_ * R_];
static __device__ float g_vos[C_ * R_];
static __device__ float g_focal[N_];
static __device__ int   g_order[C_ * N_];
static __device__ int   g_cnt[C_];
static __device__ unsigned long long g_amax[C_];
static __device__ int   g_bars[64];

// ---------------- per-class ordering + replay-state reset ----------------
__global__ void order_kernel(const int* __restrict__ labels) {
    __shared__ int labs[N_];
    int tid = threadIdx.x;                   // 512 threads
    labs[tid] = labels[tid];
    if (tid < C_) { g_cnt[tid] = 0; g_amax[tid] = 0ull; }
    if (tid < 64) g_bars[tid] = 0;
    __syncthreads();
    int lab = labs[tid];
    int pos = 0;
    for (int j = 0; j < tid; j++) pos += (labs[j] == lab) ? 1 : 0;
    g_order[lab * N_ + pos] = tid;
    atomicAdd(&g_cnt[lab], 1);
}

// ---------------- materialize updated queues (padded) ----------------
__global__ void matD_kernel(const float* __restrict__ id_data, const float* __restrict__ box) {
    int row = blockIdx.x;
    if (row >= M_) {
        ((float4*)(g_D + (size_t)row * R_))[threadIdx.x] = make_float4(0.f, 0.f, 0.f, 0.f);
        return;
    }
    int c = row / Q_, q = row - c * Q_;
    int k = g_cnt[c];
    const float* src;
    if (q < Q_ - k) src = id_data + (size_t)(c * Q_ + q + k) * R_;
    else            src = box + (size_t)g_order[c * N_ + q - (Q_ - k)] * R_;
    ((float4*)(g_D + (size_t)row * R_))[threadIdx.x] = ((const float4*)src)[threadIdx.x];
}

// ---------------- per-class mean ----------------
__global__ void mu_part_kernel() {                     // grid 250, 256 thr
    int z = blockIdx.x;
    const float4* base = (const float4*)(g_D + (size_t)z * MCH * R_);
    float4 s = make_float4(0.f, 0.f, 0.f, 0.f);
    for (int q = 0; q < MCH; q++) {
        float4 v = base[q * (R_ / 4) + threadIdx.x];
        s.x += v.x; s.y += v.y; s.z += v.z; s.w += v.w;
    }
    ((float4*)g_mup)[z * (R_ / 4) + threadIdx.x] = s;
}
__global__ void mu_reduce_kernel() {                   // grid 40, 256 thr
    int gid = blockIdx.x * 256 + threadIdx.x;
    int c = gid >> 10, r = gid & 1023;
    float s = 0.f;
#pragma unroll
    for (int z = 0; z < NMCH / C_; z++) s += g_mup[(c * (NMCH / C_) + z) * R_ + r];
    g_mu[gid] = s * (1.f / (float)Q_);
}

// ---------------- ||eps||^2 + per-class argmax, block-pre-reduced ----------------
// block = 32 consecutive rows; warp w handles rows base+w*4..+3 in 2 interleaved pairs
__global__ void sq_kernel(const float* __restrict__ eps) {   // grid 3125 x 256
    __shared__ unsigned long long keys[32];
    int tid = threadIdx.x, w = tid >> 5, lane = tid & 31;
    int rowbase = blockIdx.x * 32;
#pragma unroll
    for (int pr = 0; pr < 2; pr++) {
        int r0 = rowbase + w * 4 + pr * 2;
        const float4* p0 = (const float4*)(eps + (size_t)r0 * R_);
        const float4* p1 = (const float4*)(eps + (size_t)(r0 + 1) * R_);
        float s0 = 0.f, s1 = 0.f;
#pragma unroll
        for (int it = 0; it < 8; it++) {
            float4 a = p0[lane + it * 32];
            float4 b = p1[lane + it * 32];
            s0 = fmaf(a.x, a.x, fmaf(a.y, a.y, fmaf(a.z, a.z, fmaf(a.w, a.w, s0))));
            s1 = fmaf(b.x, b.x, fmaf(b.y, b.y, fmaf(b.z, b.z, fmaf(b.w, b.w, s1))));
        }
#pragma unroll
        for (int o = 16; o; o >>= 1) {
            s0 += __shfl_xor_sync(0xffffffffu, s0, o);
            s1 += __shfl_xor_sync(0xffffffffu, s1, o);
        }
        if (lane == 0) {
            int c0 = r0 / S_, c1 = (r0 + 1) / S_;
            unsigned i0 = (unsigned)(r0 - c0 * S_), i1 = (unsigned)(r0 + 1 - c1 * S_);
            keys[w * 4 + pr * 2] =
                ((unsigned long long)__float_as_uint(s0) << 32) | (unsigned long long)(0xFFFFFFFFu - i0);
            keys[w * 4 + pr * 2 + 1] =
                ((unsigned long long)__float_as_uint(s1) << 32) | (unsigned long long)(0xFFFFFFFFu - i1);
        }
    }
    __syncthreads();
    if (tid == 0) {
        int c0 = rowbase / S_;
        unsigned long long m0 = 0ull, m1 = 0ull;
        for (int i = 0; i < 32; i++) {
            int cls = (rowbase + i) / S_;
            unsigned long long k = keys[i];
            if (cls == c0) { if (k > m0) m0 = k; }
            else           { if (k > m1) m1 = k; }
        }
        atomicMax(&g_amax[c0], m0);
        if (m1) atomicMax(&g_amax[c0 + 1], m1);
    }
}

// ---------------- tf32 tensor-core SYRK with cp.async double buffering ----------------
__device__ __forceinline__ unsigned f2tf(float x) {
    unsigned r; asm("cvt.rna.tf32.f32 %0, %1;" : "=r"(r) : "f"(x)); return r;
}
__device__ __forceinline__ void mma_tf32(float* d, const unsigned* a, const unsigned* b) {
    asm volatile(
        "mma.sync.aligned.m16n8k8.row.col.f32.tf32.tf32.f32 "
        "{%0,%1,%2,%3}, {%4,%5,%6,%7}, {%8,%9}, {%0,%1,%2,%3};\n"
        : "+f"(d[0]), "+f"(d[1]), "+f"(d[2]), "+f"(d[3])
        : "r"(a[0]), "r"(a[1]), "r"(a[2]), "r"(a[3]), "r"(b[0]), "r"(b[1]));
}
__device__ __forceinline__ void cpasync16(unsigned saddr, const void* g) {
    asm volatile("cp.async.ca.shared.global [%0], [%1], 16;\n" :: "r"(saddr), "l"(g));
}
__device__ __forceinline__ void cp_commit() { asm volatile("cp.async.commit_group;\n"); }
__device__ __forceinline__ void cp_wait0()  { asm volatile("cp.async.wait_group 0;\n"); }

__global__ __launch_bounds__(256, 2) void syrk_kernel() {
    extern __shared__ float smem[];
    int t = blockIdx.x;
    int bi = 0;
    while ((bi + 1) * (bi + 2) / 2 <= t) bi++;
    int bj = t - bi * (bi + 1) / 2;
    bool diag = (bi == bj);

    int tid = threadIdx.x;
    int wid = tid >> 5, lane = tid & 31;
    int wy = wid & 1, wx = wid >> 1;
    int g = lane >> 2, tg = lane & 3;
    int lr = tid >> 3;
    int lc = tid & 7;

    int m0 = blockIdx.y * CHUNKP;

    float acc[4][4][4];
#pragma unroll
    for (int mf = 0; mf < 4; mf++)
#pragma unroll
        for (int nf = 0; nf < 4; nf++)
#pragma unroll
            for (int q = 0; q < 4; q++) acc[mf][nf][q] = 0.f;

    auto issue = [&](int b, int mb) {
        float* SA = smem + b * (2 * TILEF);
        float* SB = SA + TILEF;
        const float* gr = g_D + (size_t)(mb + lr) * R_;
        unsigned sA = (unsigned)__cvta_generic_to_shared(SA + lr * SSTR);
        unsigned sB = (unsigned)__cvta_generic_to_shared(SB + lr * SSTR);
#pragma unroll
        for (int i = 0; i < 4; i++) {
            int c0 = (lc + 8 * i) * 4;
            cpasync16(sA + c0 * 4, gr + bi * 128 + c0);
            if (!diag) cpasync16(sB + c0 * 4, gr + bj * 128 + c0);
        }
        cp_commit();
    };

    issue(0, m0);
    for (int s = 0; s < 40; s++) {
        int b = s & 1;
        cp_wait0();
        __syncthreads();
        if (s < 39) issue(b ^ 1, m0 + (s + 1) * 32);
        float* SA = smem + b * (2 * TILEF);
        float* SB = diag ? SA : (SA + TILEF);
#pragma unroll
        for (int ks = 0; ks < 4; ks++) {
            int k0 = ks * 8;
            unsigned af[4][4], bf[4][2];
#pragma unroll
            for (int mf = 0; mf < 4; mf++) {
                int r0 = wy * 64 + mf * 16;
                af[mf][0] = f2tf(SA[(k0 + tg) * SSTR + r0 + g]);
                af[mf][1] = f2tf(SA[(k0 + tg) * SSTR + r0 + g + 8]);
                af[mf][2] = f2tf(SA[(k0 + tg + 4) * SSTR + r0 + g]);
                af[mf][3] = f2tf(SA[(k0 + tg + 4) * SSTR + r0 + g + 8]);
            }
#pragma unroll
            for (int nf = 0; nf < 4; nf++) {
                int c0 = wx * 32 + nf * 8;
                bf[nf][0] = f2tf(SB[(k0 + tg) * SSTR + c0 + g]);
                bf[nf][1] = f2tf(SB[(k0 + tg + 4) * SSTR + c0 + g]);
            }
#pragma unroll
            for (int mf = 0; mf < 4; mf++)
#pragma unroll
                for (int nf = 0; nf < 4; nf++)
                    mma_tf32(acc[mf][nf], af[mf], bf[nf]);
        }
        __syncthreads();
    }
    float* gp = g_Gp[blockIdx.y];
#pragma unroll
    for (int mf = 0; mf < 4; mf++) {
        int r0 = bi * 128 + wy * 64 + mf * 16 + g;
#pragma unroll
        for (int nf = 0; nf < 4; nf++) {
            int c0 = bj * 128 + wx * 32 + nf * 8 + 2 * tg;
            *(float2*)&gp[(size_t)r0 * R_ + c0]       = make_float2(acc[mf][nf][0], acc[mf][nf][1]);
            *(float2*)&gp[(size_t)(r0 + 8) * R_ + c0] = make_float2(acc[mf][nf][2], acc[mf][nf][3]);
        }
    }
}

// ---------------- sigma (lower only) ----------------
__global__ void sigma_kernel() {
    int gid = blockIdx.x * 256 + threadIdx.x;
    int i = gid >> 10, j = gid & 1023;
    if (j > i) return;
    size_t lo = (size_t)i * R_ + j;
    float s = 0.f;
#pragma unroll
    for (int z = 0; z < KSPLIT; z++) s += g_Gp[z][lo];
    float corr = 0.f;
#pragma unroll
    for (int c = 0; c < C_; c++) corr += g_mu[c * R_ + i] * g_mu[c * R_ + j];
    float v = (s - (float)Q_ * corr) * (1.f / (float)M_);
    if (i == j) v += 1e-4f;
    g_S[lo] = v;
}

// ---------------- persistent blocked Cholesky (B=64, 16 panels) ----------------
__device__ __forceinline__ void grid_bar(int id) {
    __syncthreads();
    if (threadIdx.x == 0) {
        __threadfence();
        atomicAdd(&g_bars[id], 1);
        while (*(volatile int*)&g_bars[id] < CHB) { __nanosleep(32); }
        __threadfence();
    }
    __syncthreads();
}

__global__ __launch_bounds__(256) void chol_kernel() {
    __shared__ float P[64][65];
    __shared__ float invd[64];
    __shared__ float As[64][65];
    __shared__ float Bs[64][65];
    int bid = blockIdx.x, tid = threadIdx.x;
    int barid = 0;

    for (int p = 0; p < 16; p++) {
        int o = p * 64, o2 = o + 64;
        int nr = R_ - o2;

        // ---- redundant in-shared potf2 (every block) ----
        for (int idx = tid; idx < 4096; idx += 256) {
            int i = idx >> 6, j = idx & 63;
            P[i][j] = (j <= i) ? g_S[(size_t)(o + i) * R_ + o + j] : 0.f;
        }
        __syncthreads();
        for (int k = 0; k < 64; k++) {
            float d = P[k][k];
            float sd = sqrtf(d);
            int i = k + 1 + tid;
            if (i < 64) P[i][k] /= sd;
            __syncthreads();
            if (tid == 0) P[k][k] = sd;
            int n = 63 - k;
            for (int idx = tid; idx < n * 64; idx += 256) {
                int i2 = k + 1 + (idx >> 6);
                int j2 = idx & 63;
                if (j2 > k && j2 <= i2) P[i2][j2] -= P[i2][k] * P[j2][k];
            }
            __syncthreads();
        }
        if (tid < 64) invd[tid] = 1.f / P[tid][tid];
        __syncthreads();

        if (bid == 0) {
            for (int idx = tid; idx < 4096; idx += 256) {
                int i = idx >> 6, j = idx & 63;
                if (j <= i) g_S[(size_t)(o + i) * R_ + o + j] = P[i][j];
            }
        }

        // ---- TRSM rows: 8-column blocks, NAMED registers (spill-proof) ----
        if (nr > 0) {
            int rr = bid * 256 + tid;
            if (rr < nr) {
                int r = o2 + rr;
                float* gptr = g_S + (size_t)r * R_ + o;
#pragma unroll
                for (int b = 0; b < 8; b++) {
                    float* gb = gptr + b * 8;
                    float x0 = gb[0], x1 = gb[1], x2 = gb[2], x3 = gb[3],
                          x4 = gb[4], x5 = gb[5], x6 = gb[6], x7 = gb[7];
#pragma unroll
                    for (int kb = 0; kb < b; kb++) {
                        const float* hp = gptr + kb * 8;
                        float h0 = hp[0], h1 = hp[1], h2 = hp[2], h3 = hp[3],
                              h4 = hp[4], h5 = hp[5], h6 = hp[6], h7 = hp[7];
#define UPDJ(j) { const float* Lj = &P[b * 8 + (j)][kb * 8]; \
    x##j -= h0*Lj[0] + h1*Lj[1] + h2*Lj[2] + h3*Lj[3] + h4*Lj[4] + h5*Lj[5] + h6*Lj[6] + h7*Lj[7]; }
                        UPDJ(0) UPDJ(1) UPDJ(2) UPDJ(3) UPDJ(4) UPDJ(5) UPDJ(6) UPDJ(7)
#undef UPDJ
                    }
                    {
                        const int b8 = b * 8;
                        x0 *= invd[b8 + 0];
                        x1 = (x1 - x0*P[b8+1][b8+0]) * invd[b8+1];
                        x2 = (x2 - x0*P[b8+2][b8+0] - x1*P[b8+2][b8+1]) * invd[b8+2];
                        x3 = (x3 - x0*P[b8+3][b8+0] - x1*P[b8+3][b8+1] - x2*P[b8+3][b8+2]) * invd[b8+3];
                        x4 = (x4 - x0*P[b8+4][b8+0] - x1*P[b8+4][b8+1] - x2*P[b8+4][b8+2]
                                 - x3*P[b8+4][b8+3]) * invd[b8+4];
                        x5 = (x5 - x0*P[b8+5][b8+0] - x1*P[b8+5][b8+1] - x2*P[b8+5][b8+2]
                                 - x3*P[b8+5][b8+3] - x4*P[b8+5][b8+4]) * invd[b8+5];
                        x6 = (x6 - x0*P[b8+6][b8+0] - x1*P[b8+6][b8+1] - x2*P[b8+6][b8+2]
                                 - x3*P[b8+6][b8+3] - x4*P[b8+6][b8+4] - x5*P[b8+6][b8+5]) * invd[b8+6];
                        x7 = (x7 - x0*P[b8+7][b8+0] - x1*P[b8+7][b8+1] - x2*P[b8+7][b8+2]
                                 - x3*P[b8+7][b8+3] - x4*P[b8+7][b8+4] - x5*P[b8+7][b8+5]
                                 - x6*P[b8+7][b8+6]) * invd[b8+7];
                    }
                    gb[0] = x0; gb[1] = x1; gb[2] = x2; gb[3] = x3;
                    gb[4] = x4; gb[5] = x5; gb[6] = x6; gb[7] = x7;
                }
            }
        }
        grid_bar(barid++);

        // ---- trailing SYRK update ----
        if (nr > 0) {
            int nt = nr >> 6;
            int ntiles = nt * (nt + 1) / 2;
            for (int t = bid; t < ntiles; t += CHB) {
                __syncthreads();
                int bi = 0;
                while ((bi + 1) * (bi + 2) / 2 <= t) bi++;
                int bj = t - bi * (bi + 1) / 2;
                for (int idx = tid; idx < 4096; idx += 256) {
                    int i = idx >> 6, j = idx & 63;
                    As[i][j] = g_S[(size_t)(o2 + bi * 64 + i) * R_ + o + j];
                    Bs[i][j] = g_S[(size_t)(o2 + bj * 64 + i) * R_ + o + j];
                }
                __syncthreads();
                int tx = tid & 15, ty = tid >> 4;
                float acc[4][4];
#pragma unroll
                for (int r = 0; r < 4; r++)
#pragma unroll
                    for (int c = 0; c < 4; c++) acc[r][c] = 0.f;
#pragma unroll 8
                for (int k = 0; k < 64; k++) {
                    float a[4], b[4];
#pragma unroll
                    for (int r = 0; r < 4; r++) a[r] = As[ty * 4 + r][k];
#pragma unroll
                    for (int c = 0; c < 4; c++) b[c] = Bs[tx * 4 + c][k];
#pragma unroll
                    for (int r = 0; r < 4; r++)
#pragma unroll
                        for (int c = 0; c < 4; c++) acc[r][c] = fmaf(a[r], b[c], acc[r][c]);
                }
#pragma unroll
                for (int r = 0; r < 4; r++)
#pragma unroll
                    for (int c = 0; c < 4; c++)
                        g_S[(size_t)(o2 + bi * 64 + ty * 4 + r) * R_ + o2 + bj * 64 + tx * 4 + c] -= acc[r][c];
            }
        }
        grid_bar(barid++);
    }
}

// ---------------- gather selected eps ----------------
__global__ void gather_kernel(const float* __restrict__ eps) {
    int c = blockIdx.x;
    unsigned s = 0xFFFFFFFFu - (unsigned)(g_amax[c] & 0xFFFFFFFFull);
    const float4* src = (const float4*)(eps + ((size_t)c * S_ + s) * R_);
    ((float4*)(g_eps_sel + c * R_))[threadIdx.x] = src[threadIdx.x];
}

// ---------------- vos = mu + L @ eps_sel ----------------
__global__ void vos_kernel() {                  // grid 16 x 256
    __shared__ float e[C_][R_];
    int tid = threadIdx.x;
    for (int i = tid; i < C_ * R_; i += 256) ((float*)e)[i] = g_eps_sel[i];
    __syncthreads();
    int w = tid >> 5, lane = tid & 31;
    for (int rr = 0; rr < 8; rr++) {
        int i = blockIdx.x * 64 + rr * 8 + w;
        const float* Lr = g_S + (size_t)i * R_;
        float p[C_];
#pragma unroll
        for (int c = 0; c < C_; c++) p[c] = 0.f;
        for (int j = lane; j <= i; j += 32) {
            float Lv = Lr[j];
#pragma unroll
            for (int c = 0; c < C_; c++) p[c] = fmaf(Lv, e[c][j], p[c]);
        }
#pragma unroll
        for (int c = 0; c < C_; c++) {
            float v = p[c];
#pragma unroll
            for (int o = 16; o; o >>= 1) v += __shfl_xor_sync(0xffffffffu, v, o);
            if (lane == 0) g_vos[c * R_ + i] = g_mu[c * R_ + i] + v;
        }
    }
}

// ---------------- scores + focal (cls path) ----------------
__global__ void scores_cls_kernel(const float* __restrict__ X, const float* __restrict__ W,
                                  const float* __restrict__ b, const int* __restrict__ labels) {
    __shared__ float red[C_][8];
    __shared__ float srow[C_];
    int row = blockIdx.x, tid = threadIdx.x;
    float acc[C_];
#pragma unroll
    for (int c = 0; c < C_; c++) acc[c] = 0.f;
    const float* x = X + (size_t)row * R_;
    for (int r = tid; r < R_; r += 256) {
        float xv = x[r];
#pragma unroll
        for (int c = 0; c < C_; c++) acc[c] = fmaf(xv, W[c * R_ + r], acc[c]);
    }
#pragma unroll
    for (int c = 0; c < C_; c++) {
        float v = acc[c];
#pragma unroll
        for (int o = 16; o; o >>= 1) v += __shfl_xor_sync(0xffffffffu, v, o);
        acc[c] = v;
    }
    int w = tid >> 5, lane = tid & 31;
    if (lane == 0)
#pragma unroll
        for (int c = 0; c < C_; c++) red[c][w] = acc[c];
    __syncthreads();
    if (tid < C_) {
        float s = red[tid][0];
#pragma unroll
        for (int ww = 1; ww < 8; ww++) s += red[tid][ww];
        s += b[tid];
        g_scores[row * C_ + tid] = s;
        srow[tid] = s;
    }
    __syncthreads();
    if (tid == 0) {
        int lab = labels[row];
        float fs = 0.f;
#pragma unroll
        for (int c = 0; c < C_; c++) {
            float xv = srow[c];
            float tt = (c == lab) ? 1.f : 0.f;
            float ce = fmaxf(xv, 0.f) - xv * tt + log1pf(expf(-fabsf(xv)));
            float pp = 1.f / (1.f + expf(-xv));
            float pt = pp * tt + (1.f - pp) * (1.f - tt);
            float at = 0.25f * tt + 0.75f * (1.f - tt);
            float om = 1.f - pt;
            fs += at * ce * om * om;
        }
        g_focal[row] = fs;
    }
}

// ---------------- scores_vos ----------------
__global__ void scores_vos_kernel(const float* __restrict__ W, const float* __restrict__ b) {
    __shared__ float red[C_][8];
    int row = blockIdx.x, tid = threadIdx.x;
    float acc[C_];
#pragma unroll
    for (int c = 0; c < C_; c++) acc[c] = 0.f;
    const float* x = g_vos + (size_t)row * R_;
    for (int r = tid; r < R_; r += 256) {
        float xv = x[r];
#pragma unroll
        for (int c = 0; c < C_; c++) acc[c] = fmaf(xv, W[c * R_ + r], acc[c]);
    }
#pragma unroll
    for (int c = 0; c < C_; c++) {
        float v = acc[c];
#pragma unroll
        for (int o = 16; o; o >>= 1) v += __shfl_xor_sync(0xffffffffu, v, o);
        acc[c] = v;
    }
    int w = tid >> 5, lane = tid & 31;
    if (lane == 0)
#pragma unroll
        for (int c = 0; c < C_; c++) red[c][w] = acc[c];
    __syncthreads();
    if (tid < C_) {
        float s = red[tid][0];
#pragma unroll
        for (int ww = 1; ww < 8; ww++) s += red[tid][ww];
        g_scores_vos[row * C_ + tid] = s + b[tid];
    }
}

// ---------------- energy -> MLP -> BCE + focal reduction ----------------
__global__ void final_kernel(const float* __restrict__ w_e, const float* __restrict__ W1,
                             const float* __restrict__ b1, const float* __restrict__ W2,
                             const float* __restrict__ b2, float* __restrict__ out) {
    __shared__ float we[C_];
    __shared__ float bce[544];
    __shared__ float foc[N_];
    int tid = threadIdx.x;                      // 544 threads
    if (tid < C_) we[tid] = fmaxf(w_e[tid], 0.f);
    for (int i = tid; i < N_; i += 544) foc[i] = g_focal[i];
    __syncthreads();
    float v = 0.f;
    if (tid < N_ + C_) {
        const float* row = (tid < N_) ? (g_scores + tid * C_) : (g_scores_vos + (tid - N_) * C_);
        float m = row[0];
#pragma unroll
        for (int c = 1; c < C_; c++) m = fmaxf(m, row[c]);
        float ssum = 0.f;
#pragma unroll
        for (int c = 0; c < C_; c++) ssum += expf(row[c] - m) * we[c];
        float e = m + logf(ssum);
        float lg = 0.f;
        for (int j = 0; j < 512; j++) lg = fmaf(fmaxf(fmaf(e, W1[j], b1[j]), 0.f), W2[j], lg);
        lg += b2[0];
        float y = (tid < N_) ? 1.f : 0.f;
        v = fmaxf(lg, 0.f) - lg * y + log1pf(expf(-fabsf(lg)));
    }
    bce[tid] = v;
    __syncthreads();
    if (tid == 0) {
        float bs = 0.f;
        for (int i = 0; i < N_ + C_; i++) bs += bce[i];
        float fsum = 0.f;
        for (int i = 0; i < N_; i++) fsum += foc[i];
        out[0] = fsum / (float)N_;
        out[1] = 0.1f * bs / (float)(N_ + C_);
    }
}

// ---------------- launch ----------------
extern "C" void kernel_launch(void* const* d_in, const int* in_sizes, int n_in,
                              void* d_out, int out_size) {
    const float* box     = (const float*)d_in[0];
    const int*   labels  = (const int*)d_in[1];
    const float* id_data = (const float*)d_in[2];
    const float* W_pred  = (const float*)d_in[4];
    const float* b_pred  = (const float*)d_in[5];
    const float* w_e     = (const float*)d_in[6];
    const float* dW1     = (const float*)d_in[7];
    const float* db1     = (const float*)d_in[8];
    const float* dW2     = (const float*)d_in[9];
    const float* db2     = (const float*)d_in[10];
    const float* eps     = (const float*)d_in[11];
    float* out = (float*)d_out;
    (void)in_sizes; (void)n_in; (void)out_size;

    cudaFuncSetAttribute(syrk_kernel, cudaFuncAttributeMaxDynamicSharedMemorySize, SYRK_SMEM);

    order_kernel<<<1, 512>>>(labels);                       // 1
    matD_kernel<<<MP, 256>>>(id_data, box);                 // 2
    mu_part_kernel<<<NMCH, 256>>>();                        // 3
    sq_kernel<<<3125, 256>>>(eps);                          // 4  <- profiled
    syrk_kernel<<<dim3(36, KSPLIT), 256, SYRK_SMEM>>>();    // 5
    mu_reduce_kernel<<<(C_ * R_) / 256, 256>>>();           // 6
    sigma_kernel<<<(R_ * R_) / 256, 256>>>();               // 7
    chol_kernel<<<CHB, 256>>>();                            // 8
    gather_kernel<<<C_, 256>>>(eps);                        // 9
    vos_kernel<<<16, 256>>>();                              // 10
    scores_cls_kernel<<<N_, 256>>>(box, W_pred, b_pred, labels); // 11
    scores_vos_kernel<<<C_, 256>>>(W_pred, b_pred);         // 12
    final_kernel<<<1, 544>>>(w_e, dW1, db1, dW2, db2, out); // 13
}